// round 3
// baseline (speedup 1.0000x reference)
#include <cuda_runtime.h>
#include <cstdint>

#define BATCH 4
#define HEADS 8
#define SEQ   3137          // 1 cls + 56*56
#define HD    32
#define CDIM  256
#define HW    56
#define NPIX  (HW*HW)       // 3136
#define MTOT  (BATCH*SEQ)   // 12548
#define QKV_N 768

// ---------------- scratch (device globals; no allocation allowed) ----------
__device__ float g_Q[(size_t)BATCH*HEADS*SEQ*HD];
__device__ float g_K[(size_t)BATCH*HEADS*SEQ*HD];
__device__ float g_V[(size_t)BATCH*HEADS*SEQ*HD];
__device__ float g_O[(size_t)BATCH*SEQ*CDIM];

// ---------------------------------------------------------------------------
// Kernel 1: QKV GEMM.  A = concat(cls, x) rows (M=12548, K=256),
// W = qkv_w (768 x 256), C[m][n] = dot(A[m,:], W[n,:]).
// Scatter into g_Q/g_K/g_V with layout (b, head, s, d); Q pre-scaled.
// Tiling: 64x64x16, 256 threads, 4x4 per thread.
// ---------------------------------------------------------------------------
__global__ __launch_bounds__(256) void qkv_gemm_kernel(
    const float* __restrict__ x, const float* __restrict__ cls,
    const float* __restrict__ w)
{
    __shared__ float Ash[16][64];
    __shared__ float Wsh[16][64];

    const int t  = threadIdx.x;
    const int tx = t & 15;
    const int ty = t >> 4;
    const int rowBase = blockIdx.x * 64;
    const int colBase = blockIdx.y * 64;

    // loader mapping: thread loads A/W row lm, k-chunk lk..lk+3
    const int lm = t >> 2;
    const int lk = (t & 3) * 4;

    const float* arow = nullptr;
    {
        int gr = rowBase + lm;
        if (gr < MTOT) {
            int b = gr / SEQ, s = gr % SEQ;
            arow = (s == 0) ? (cls + (size_t)b * CDIM)
                            : (x + ((size_t)b * NPIX + (s - 1)) * CDIM);
        }
    }
    const float* wrow = w + (size_t)(colBase + lm) * CDIM;

    float acc[4][4] = {};

    for (int k0 = 0; k0 < CDIM; k0 += 16) {
        float4 av = arow ? *(const float4*)(arow + k0 + lk)
                         : make_float4(0.f, 0.f, 0.f, 0.f);
        float4 wv = *(const float4*)(wrow + k0 + lk);
        __syncthreads();
        Ash[lk + 0][lm] = av.x; Ash[lk + 1][lm] = av.y;
        Ash[lk + 2][lm] = av.z; Ash[lk + 3][lm] = av.w;
        Wsh[lk + 0][lm] = wv.x; Wsh[lk + 1][lm] = wv.y;
        Wsh[lk + 2][lm] = wv.z; Wsh[lk + 3][lm] = wv.w;
        __syncthreads();
#pragma unroll
        for (int kk = 0; kk < 16; kk++) {
            float4 a4 = *(const float4*)&Ash[kk][ty * 4];
            float4 w4 = *(const float4*)&Wsh[kk][tx * 4];
            float av_[4] = {a4.x, a4.y, a4.z, a4.w};
            float wv_[4] = {w4.x, w4.y, w4.z, w4.w};
#pragma unroll
            for (int i = 0; i < 4; i++)
#pragma unroll
                for (int j = 0; j < 4; j++)
                    acc[i][j] = fmaf(av_[i], wv_[j], acc[i][j]);
        }
    }

    const float scale = 0.17677669529663689f;  // 32^-0.5
#pragma unroll
    for (int i = 0; i < 4; i++) {
        int r = rowBase + ty * 4 + i;
        if (r >= MTOT) continue;
        int b = r / SEQ, s = r % SEQ;
#pragma unroll
        for (int j = 0; j < 4; j++) {
            int col   = colBase + tx * 4 + j;
            int which = col >> 8;
            int f     = col & 255;
            int head  = f >> 5;
            int d     = f & 31;
            size_t dst = (((size_t)(b * HEADS + head)) * SEQ + s) * HD + d;
            float v = acc[i][j];
            if (which == 0)      g_Q[dst] = v * scale;
            else if (which == 1) g_K[dst] = v;
            else                 g_V[dst] = v;
        }
    }
}

// ---------------------------------------------------------------------------
// Kernel 2: flash attention, fp32. Block = (qtile, head, batch), 256 thr.
// BQ = BKEY = 64, hd = 32. Each thread owns (query q = t%64, 8 dims).
// ---------------------------------------------------------------------------
__global__ __launch_bounds__(256) void flash_attn_kernel()
{
    const int b  = blockIdx.z;
    const int h  = blockIdx.y;
    const int qt = blockIdx.x;

    const float* Qg = g_Q + ((size_t)(b * HEADS + h)) * SEQ * HD;
    const float* Kg = g_K + ((size_t)(b * HEADS + h)) * SEQ * HD;
    const float* Vg = g_V + ((size_t)(b * HEADS + h)) * SEQ * HD;

    __shared__ float Qts[HD][64];      // transposed: [d][q]
    __shared__ float Kts[HD][64];      // transposed: [d][k]
    __shared__ float Vs[64][HD];       // row-major
    __shared__ float Ss[64][65];       // scores, padded

    const int t    = threadIdx.x;
    const int q    = t & 63;
    const int dblk = t >> 6;           // 0..3
    const int d0   = dblk * 8;
    const int tyq  = t >> 4;           // 0..15 (4 queries each)
    const int txk  = t & 15;           // 0..15 (4 keys each)

    const int qg = qt * 64 + q;

    // stage Q tile (transposed)
    {
        float4 v0 = make_float4(0.f,0.f,0.f,0.f), v1 = v0;
        if (qg < SEQ) {
            const float* p = Qg + (size_t)qg * HD + d0;
            v0 = *(const float4*)p;
            v1 = *(const float4*)(p + 4);
        }
        Qts[d0+0][q]=v0.x; Qts[d0+1][q]=v0.y; Qts[d0+2][q]=v0.z; Qts[d0+3][q]=v0.w;
        Qts[d0+4][q]=v1.x; Qts[d0+5][q]=v1.y; Qts[d0+6][q]=v1.z; Qts[d0+7][q]=v1.w;
    }

    float acc[8] = {0.f,0.f,0.f,0.f,0.f,0.f,0.f,0.f};
    float mrow = -1e30f, lrow = 0.f;

    const int NKT = (SEQ + 63) / 64;   // 50
    for (int kt = 0; kt < NKT; kt++) {
        const int kbase = kt * 64;
        // stage K (transposed) and V tiles — thread loads row q, dims d0..d0+7
        float4 k0 = make_float4(0.f,0.f,0.f,0.f), k1 = k0, w0 = k0, w1 = k0;
        {
            int kg = kbase + q;
            if (kg < SEQ) {
                const float* kp = Kg + (size_t)kg * HD + d0;
                k0 = *(const float4*)kp;  k1 = *(const float4*)(kp + 4);
                const float* vp = Vg + (size_t)kg * HD + d0;
                w0 = *(const float4*)vp;  w1 = *(const float4*)(vp + 4);
            }
        }
        Kts[d0+0][q]=k0.x; Kts[d0+1][q]=k0.y; Kts[d0+2][q]=k0.z; Kts[d0+3][q]=k0.w;
        Kts[d0+4][q]=k1.x; Kts[d0+5][q]=k1.y; Kts[d0+6][q]=k1.z; Kts[d0+7][q]=k1.w;
        *(float4*)&Vs[q][d0]     = w0;
        *(float4*)&Vs[q][d0 + 4] = w1;
        __syncthreads();

        // S = Q K^T : 4x4 micro-tile per thread
        float sacc[4][4] = {};
#pragma unroll
        for (int d = 0; d < HD; d++) {
            float4 a4 = *(const float4*)&Qts[d][tyq * 4];
            float4 b4 = *(const float4*)&Kts[d][txk * 4];
            float av_[4] = {a4.x, a4.y, a4.z, a4.w};
            float bv_[4] = {b4.x, b4.y, b4.z, b4.w};
#pragma unroll
            for (int i = 0; i < 4; i++)
#pragma unroll
                for (int j = 0; j < 4; j++)
                    sacc[i][j] = fmaf(av_[i], bv_[j], sacc[i][j]);
        }
#pragma unroll
        for (int i = 0; i < 4; i++)
#pragma unroll
            for (int j = 0; j < 4; j++) {
                int kcol = txk * 4 + j;
                Ss[tyq * 4 + i][kcol] =
                    (kbase + kcol < SEQ) ? sacc[i][j] : -1e30f;
            }
        __syncthreads();

        // online softmax + P*V (4 threads per query, consistent redundant l/m)
        float mloc = mrow;
#pragma unroll 8
        for (int j = 0; j < 64; j++) mloc = fmaxf(mloc, Ss[q][j]);
        float corr = __expf(mrow - mloc);
        lrow *= corr;
#pragma unroll
        for (int i = 0; i < 8; i++) acc[i] *= corr;
        float lsum = 0.f;
#pragma unroll 4
        for (int j = 0; j < 64; j++) {
            float p = __expf(Ss[q][j] - mloc);
            lsum += p;
            float4 v0 = *(const float4*)&Vs[j][d0];
            float4 v1 = *(const float4*)&Vs[j][d0 + 4];
            acc[0] = fmaf(p, v0.x, acc[0]); acc[1] = fmaf(p, v0.y, acc[1]);
            acc[2] = fmaf(p, v0.z, acc[2]); acc[3] = fmaf(p, v0.w, acc[3]);
            acc[4] = fmaf(p, v1.x, acc[4]); acc[5] = fmaf(p, v1.y, acc[5]);
            acc[6] = fmaf(p, v1.z, acc[6]); acc[7] = fmaf(p, v1.w, acc[7]);
        }
        lrow += lsum;
        mrow = mloc;
        __syncthreads();
    }

    if (qg < SEQ) {
        float inv = 1.f / lrow;
        float* outp = g_O + ((size_t)b * SEQ + qg) * CDIM + h * HD + d0;
#pragma unroll
        for (int i = 0; i < 8; i++) outp[i] = acc[i] * inv;
    }
}

// ---------------------------------------------------------------------------
// Kernel 3: depthwise 5x5 LePE (NHWC, SAME), adds into g_O rows 1..3136.
// Block = 256 threads (one channel each), 8 pixels per block.
// ---------------------------------------------------------------------------
__global__ __launch_bounds__(256) void lepe_kernel(
    const float* __restrict__ x, const float* __restrict__ w,
    const float* __restrict__ bias)
{
    __shared__ float ws[CDIM * 25];
    const int c = threadIdx.x;
    for (int idx = c; idx < CDIM * 25; idx += 256) ws[idx] = w[idx];
    __syncthreads();

    const int blk  = blockIdx.x;         // 0 .. 4*56*7-1
    const int b    = blk / (HW * 7);
    const int rem  = blk % (HW * 7);
    const int hh   = rem / 7;
    const int ww0  = (rem % 7) * 8;
    const float bc = bias[c];

#pragma unroll
    for (int p = 0; p < 8; p++) {
        int ww = ww0 + p;
        float sum = bc;
#pragma unroll
        for (int dy = 0; dy < 5; dy++) {
            int y = hh + dy - 2;
            if (y < 0 || y >= HW) continue;
#pragma unroll
            for (int dx = 0; dx < 5; dx++) {
                int xx = ww + dx - 2;
                if (xx < 0 || xx >= HW) continue;
                sum = fmaf(x[(((size_t)b * HW + y) * HW + xx) * CDIM + c],
                           ws[c * 25 + dy * 5 + dx], sum);
            }
        }
        int hw = hh * HW + ww;
        g_O[((size_t)b * SEQ + 1 + hw) * CDIM + c] += sum;
    }
}

// ---------------------------------------------------------------------------
// Kernel 4: proj GEMM. A = g_O (12548 x 256), W = proj_w (256 x 256), +bias.
// Rows s==0 -> cls_out block; rows s>0 -> x_out block.
// ---------------------------------------------------------------------------
__global__ __launch_bounds__(256) void proj_gemm_kernel(
    const float* __restrict__ w, const float* __restrict__ bias,
    float* __restrict__ out)
{
    __shared__ float Ash[16][64];
    __shared__ float Wsh[16][64];

    const int t  = threadIdx.x;
    const int tx = t & 15;
    const int ty = t >> 4;
    const int rowBase = blockIdx.x * 64;
    const int colBase = blockIdx.y * 64;

    const int lm = t >> 2;
    const int lk = (t & 3) * 4;

    const float* arow = (rowBase + lm < MTOT)
                      ? (g_O + (size_t)(rowBase + lm) * CDIM) : nullptr;
    const float* wrow = w + (size_t)(colBase + lm) * CDIM;

    float acc[4][4] = {};

    for (int k0 = 0; k0 < CDIM; k0 += 16) {
        float4 av = arow ? *(const float4*)(arow + k0 + lk)
                         : make_float4(0.f, 0.f, 0.f, 0.f);
        float4 wv = *(const float4*)(wrow + k0 + lk);
        __syncthreads();
        Ash[lk + 0][lm] = av.x; Ash[lk + 1][lm] = av.y;
        Ash[lk + 2][lm] = av.z; Ash[lk + 3][lm] = av.w;
        Wsh[lk + 0][lm] = wv.x; Wsh[lk + 1][lm] = wv.y;
        Wsh[lk + 2][lm] = wv.z; Wsh[lk + 3][lm] = wv.w;
        __syncthreads();
#pragma unroll
        for (int kk = 0; kk < 16; kk++) {
            float4 a4 = *(const float4*)&Ash[kk][ty * 4];
            float4 w4 = *(const float4*)&Wsh[kk][tx * 4];
            float av_[4] = {a4.x, a4.y, a4.z, a4.w};
            float wv_[4] = {w4.x, w4.y, w4.z, w4.w};
#pragma unroll
            for (int i = 0; i < 4; i++)
#pragma unroll
                for (int j = 0; j < 4; j++)
                    acc[i][j] = fmaf(av_[i], wv_[j], acc[i][j]);
        }
    }

    const size_t cls_off = (size_t)BATCH * NPIX * CDIM;   // 3,211,264
#pragma unroll
    for (int i = 0; i < 4; i++) {
        int r = rowBase + ty * 4 + i;
        if (r >= MTOT) continue;
        int b = r / SEQ, s = r % SEQ;
#pragma unroll
        for (int j = 0; j < 4; j++) {
            int col = colBase + tx * 4 + j;
            float v = acc[i][j] + bias[col];
            size_t dst = (s == 0)
                       ? cls_off + (size_t)b * CDIM + col
                       : ((size_t)b * NPIX + (s - 1)) * CDIM + col;
            out[dst] = v;
        }
    }
}

// ---------------------------------------------------------------------------
extern "C" void kernel_launch(void* const* d_in, const int* in_sizes, int n_in,
                              void* d_out, int out_size)
{
    const float* x      = (const float*)d_in[0];
    const float* cls    = (const float*)d_in[1];
    const float* qkv_w  = (const float*)d_in[2];
    const float* proj_w = (const float*)d_in[3];
    const float* proj_b = (const float*)d_in[4];
    const float* lepe_w = (const float*)d_in[5];
    const float* lepe_b = (const float*)d_in[6];
    float* out = (float*)d_out;

    dim3 g1((MTOT + 63) / 64, QKV_N / 64);        // 197 x 12
    qkv_gemm_kernel<<<g1, 256>>>(x, cls, qkv_w);

    dim3 g2((SEQ + 63) / 64, HEADS, BATCH);       // 50 x 8 x 4
    flash_attn_kernel<<<g2, 256>>>();

    lepe_kernel<<<BATCH * HW * 7, 256>>>(x, lepe_w, lepe_b);

    dim3 g4((MTOT + 63) / 64, CDIM / 64);         // 197 x 4
    proj_gemm_kernel<<<g4, 256>>>(proj_w, proj_b, out);
}

// round 6
// speedup vs baseline: 1.0619x; 1.0619x over previous
#include <cuda_runtime.h>
#include <cstdint>

#define BATCH 4
#define HEADS 8
#define SEQ   3137          // 1 cls + 56*56
#define HD    32
#define CDIM  256
#define HW    56
#define NPIX  (HW*HW)       // 3136
#define MTOT  (BATCH*SEQ)   // 12548
#define QKV_N 768

typedef unsigned long long u64;

// ---------------- packed fp32x2 helpers (sm_100+ f32x2 pipe) ---------------
__device__ __forceinline__ u64 packdup(float x) {
    u64 r; asm("mov.b64 %0, {%1, %1};" : "=l"(r) : "f"(x)); return r;
}
__device__ __forceinline__ void fma2(u64 &d, u64 a, u64 b) {
    asm("fma.rn.f32x2 %0, %1, %2, %0;" : "+l"(d) : "l"(a), "l"(b));
}
__device__ __forceinline__ u64 mul2(u64 a, u64 b) {
    u64 r; asm("mul.rn.f32x2 %0, %1, %2;" : "=l"(r) : "l"(a), "l"(b)); return r;
}
__device__ __forceinline__ void unpack2(u64 v, float &x, float &y) {
    asm("mov.b64 {%0, %1}, %2;" : "=f"(x), "=f"(y) : "l"(v));
}
__device__ __forceinline__ void lds2(u64 &a, u64 &b, const void *p) {
    unsigned addr = (unsigned)__cvta_generic_to_shared(p);
    asm volatile("ld.shared.v2.u64 {%0, %1}, [%2];" : "=l"(a), "=l"(b) : "r"(addr));
}

// ---------------- scratch (device globals; no allocation allowed) ----------
__device__ float g_Q[(size_t)BATCH*HEADS*SEQ*HD];
__device__ float g_K[(size_t)BATCH*HEADS*SEQ*HD];
__device__ float g_V[(size_t)BATCH*HEADS*SEQ*HD];
__device__ float g_O[(size_t)BATCH*SEQ*CDIM];

// ---------------------------------------------------------------------------
// Kernel 1: QKV GEMM (M=12548, N=768, K=256), packed f32x2 micro-kernel.
// Scatter into g_Q/g_K/g_V with layout (b, head, s, d); Q pre-scaled.
// ---------------------------------------------------------------------------
__global__ __launch_bounds__(256) void qkv_gemm_kernel(
    const float* __restrict__ x, const float* __restrict__ cls,
    const float* __restrict__ w)
{
    __shared__ float Ash[16][64];
    __shared__ float Wsh[16][64];

    const int t  = threadIdx.x;
    const int tx = t & 15;
    const int ty = t >> 4;
    const int rowBase = blockIdx.x * 64;
    const int colBase = blockIdx.y * 64;

    const int lm = t >> 2;
    const int lk = (t & 3) * 4;

    const float* arow = nullptr;
    {
        int gr = rowBase + lm;
        if (gr < MTOT) {
            int b = gr / SEQ, s = gr % SEQ;
            arow = (s == 0) ? (cls + (size_t)b * CDIM)
                            : (x + ((size_t)b * NPIX + (s - 1)) * CDIM);
        }
    }
    const float* wrow = w + (size_t)(colBase + lm) * CDIM;

    u64 accp[4][2] = {};

    for (int k0 = 0; k0 < CDIM; k0 += 16) {
        float4 av = arow ? *(const float4*)(arow + k0 + lk)
                         : make_float4(0.f, 0.f, 0.f, 0.f);
        float4 wv = *(const float4*)(wrow + k0 + lk);
        __syncthreads();
        Ash[lk + 0][lm] = av.x; Ash[lk + 1][lm] = av.y;
        Ash[lk + 2][lm] = av.z; Ash[lk + 3][lm] = av.w;
        Wsh[lk + 0][lm] = wv.x; Wsh[lk + 1][lm] = wv.y;
        Wsh[lk + 2][lm] = wv.z; Wsh[lk + 3][lm] = wv.w;
        __syncthreads();
#pragma unroll
        for (int kk = 0; kk < 16; kk++) {
            float4 a4 = *(const float4*)&Ash[kk][ty * 4];
            u64 w01, w23; lds2(w01, w23, &Wsh[kk][tx * 4]);
            u64 aD;
            aD = packdup(a4.x); fma2(accp[0][0], aD, w01); fma2(accp[0][1], aD, w23);
            aD = packdup(a4.y); fma2(accp[1][0], aD, w01); fma2(accp[1][1], aD, w23);
            aD = packdup(a4.z); fma2(accp[2][0], aD, w01); fma2(accp[2][1], aD, w23);
            aD = packdup(a4.w); fma2(accp[3][0], aD, w01); fma2(accp[3][1], aD, w23);
        }
    }

    const float scale = 0.17677669529663689f;  // 32^-0.5
#pragma unroll
    for (int i = 0; i < 4; i++) {
        int r = rowBase + ty * 4 + i;
        if (r >= MTOT) continue;
        int b = r / SEQ, s = r % SEQ;
        float vals[4];
        unpack2(accp[i][0], vals[0], vals[1]);
        unpack2(accp[i][1], vals[2], vals[3]);
#pragma unroll
        for (int j = 0; j < 4; j++) {
            int col   = colBase + tx * 4 + j;
            int which = col >> 8;
            int f     = col & 255;
            int head  = f >> 5;
            int d     = f & 31;
            size_t dst = (((size_t)(b * HEADS + head)) * SEQ + s) * HD + d;
            float v = vals[j];
            if (which == 0)      g_Q[dst] = v * scale;
            else if (which == 1) g_K[dst] = v;
            else                 g_V[dst] = v;
        }
    }
}

// ---------------------------------------------------------------------------
// Kernel 2: flash attention, fp32, packed f32x2, single-exp softmax.
// Block = (qtile, head, batch), 256 threads. BQ = BK = 64, hd = 32.
// ---------------------------------------------------------------------------
__global__ __launch_bounds__(256) void flash_attn_kernel()
{
    const int b  = blockIdx.z;
    const int h  = blockIdx.y;
    const int qt = blockIdx.x;

    const float* Qg = g_Q + ((size_t)(b * HEADS + h)) * SEQ * HD;
    const float* Kg = g_K + ((size_t)(b * HEADS + h)) * SEQ * HD;
    const float* Vg = g_V + ((size_t)(b * HEADS + h)) * SEQ * HD;

    __shared__ float Qts[HD][64];      // transposed: [d][q]
    __shared__ float Kts[HD][64];      // transposed: [d][k]
    __shared__ float Vs[64][HD];       // row-major
    __shared__ float Ss[64][68];       // scores -> probabilities
    __shared__ float corr_sh[64];
    __shared__ float lfin_sh[64];

    const int t    = threadIdx.x;
    const int q    = t & 63;           // PV mapping: query
    const int d0   = (t >> 6) * 8;     // PV mapping: dim block
    const int tyq  = t >> 4;           // QK micro-tile row group
    const int txk  = t & 15;           // QK micro-tile col group
    const int sq   = t >> 2;           // softmax mapping: query
    const int sc   = t & 3;            // softmax mapping: chunk
    const int j0   = sc * 16;

    const int qg = qt * 64 + q;

    // stage Q tile (transposed)
    {
        float4 v0 = make_float4(0.f,0.f,0.f,0.f), v1 = v0;
        if (qg < SEQ) {
            const float* p = Qg + (size_t)qg * HD + d0;
            v0 = *(const float4*)p;
            v1 = *(const float4*)(p + 4);
        }
        Qts[d0+0][q]=v0.x; Qts[d0+1][q]=v0.y; Qts[d0+2][q]=v0.z; Qts[d0+3][q]=v0.w;
        Qts[d0+4][q]=v1.x; Qts[d0+5][q]=v1.y; Qts[d0+6][q]=v1.z; Qts[d0+7][q]=v1.w;
    }

    u64 acc[4] = {0ull, 0ull, 0ull, 0ull};   // 8 dims as 4 packed pairs
    float m_run = -1e30f, l_run = 0.f;        // per-sq, replicated in 4 threads

    const int NKT = (SEQ + 63) / 64;   // 50
    for (int kt = 0; kt < NKT; kt++) {
        const int kbase = kt * 64;

        // ---- stage K (transposed) + V ----
        {
            float4 k0 = make_float4(0.f,0.f,0.f,0.f), k1 = k0, w0 = k0, w1 = k0;
            int kg = kbase + q;
            if (kg < SEQ) {
                const float* kp = Kg + (size_t)kg * HD + d0;
                k0 = *(const float4*)kp;  k1 = *(const float4*)(kp + 4);
                const float* vp = Vg + (size_t)kg * HD + d0;
                w0 = *(const float4*)vp;  w1 = *(const float4*)(vp + 4);
            }
            Kts[d0+0][q]=k0.x; Kts[d0+1][q]=k0.y; Kts[d0+2][q]=k0.z; Kts[d0+3][q]=k0.w;
            Kts[d0+4][q]=k1.x; Kts[d0+5][q]=k1.y; Kts[d0+6][q]=k1.z; Kts[d0+7][q]=k1.w;
            *(float4*)&Vs[q][d0]     = w0;
            *(float4*)&Vs[q][d0 + 4] = w1;
        }
        __syncthreads();

        // ---- S = Q K^T (4x4 micro-tile, f32x2) ----
        u64 sp[4][2] = {};
#pragma unroll
        for (int d = 0; d < HD; d++) {
            float4 a4 = *(const float4*)&Qts[d][tyq * 4];
            u64 b01, b23; lds2(b01, b23, &Kts[d][txk * 4]);
            u64 aD;
            aD = packdup(a4.x); fma2(sp[0][0], aD, b01); fma2(sp[0][1], aD, b23);
            aD = packdup(a4.y); fma2(sp[1][0], aD, b01); fma2(sp[1][1], aD, b23);
            aD = packdup(a4.z); fma2(sp[2][0], aD, b01); fma2(sp[2][1], aD, b23);
            aD = packdup(a4.w); fma2(sp[3][0], aD, b01); fma2(sp[3][1], aD, b23);
        }
#pragma unroll
        for (int i = 0; i < 4; i++) {
            float s0, s1, s2, s3;
            unpack2(sp[i][0], s0, s1);
            unpack2(sp[i][1], s2, s3);
            int kc = kbase + txk * 4;
            float4 sv;
            sv.x = (kc + 0 < SEQ) ? s0 : -1e30f;
            sv.y = (kc + 1 < SEQ) ? s1 : -1e30f;
            sv.z = (kc + 2 < SEQ) ? s2 : -1e30f;
            sv.w = (kc + 3 < SEQ) ? s3 : -1e30f;
            *(float4*)&Ss[tyq * 4 + i][txk * 4] = sv;
        }
        __syncthreads();

        // ---- softmax: 4 threads per query, 16 scores each, exp ONCE ----
        {
            float4 s0 = *(const float4*)&Ss[sq][j0 + 0];
            float4 s1 = *(const float4*)&Ss[sq][j0 + 4];
            float4 s2 = *(const float4*)&Ss[sq][j0 + 8];
            float4 s3 = *(const float4*)&Ss[sq][j0 + 12];
            float mx = fmaxf(fmaxf(fmaxf(s0.x, s0.y), fmaxf(s0.z, s0.w)),
                             fmaxf(fmaxf(s1.x, s1.y), fmaxf(s1.z, s1.w)));
            mx = fmaxf(mx, fmaxf(fmaxf(fmaxf(s2.x, s2.y), fmaxf(s2.z, s2.w)),
                                 fmaxf(fmaxf(s3.x, s3.y), fmaxf(s3.z, s3.w))));
            mx = fmaxf(mx, __shfl_xor_sync(0xffffffffu, mx, 1));
            mx = fmaxf(mx, __shfl_xor_sync(0xffffffffu, mx, 2));
            float mnew = fmaxf(m_run, mx);
            float corr = __expf(m_run - mnew);

            float4 e0, e1, e2, e3;
            e0.x = __expf(s0.x - mnew); e0.y = __expf(s0.y - mnew);
            e0.z = __expf(s0.z - mnew); e0.w = __expf(s0.w - mnew);
            e1.x = __expf(s1.x - mnew); e1.y = __expf(s1.y - mnew);
            e1.z = __expf(s1.z - mnew); e1.w = __expf(s1.w - mnew);
            e2.x = __expf(s2.x - mnew); e2.y = __expf(s2.y - mnew);
            e2.z = __expf(s2.z - mnew); e2.w = __expf(s2.w - mnew);
            e3.x = __expf(s3.x - mnew); e3.y = __expf(s3.y - mnew);
            e3.z = __expf(s3.z - mnew); e3.w = __expf(s3.w - mnew);
            float ls = (((e0.x + e0.y) + (e0.z + e0.w)) + ((e1.x + e1.y) + (e1.z + e1.w)))
                     + (((e2.x + e2.y) + (e2.z + e2.w)) + ((e3.x + e3.y) + (e3.z + e3.w)));
            *(float4*)&Ss[sq][j0 + 0]  = e0;
            *(float4*)&Ss[sq][j0 + 4]  = e1;
            *(float4*)&Ss[sq][j0 + 8]  = e2;
            *(float4*)&Ss[sq][j0 + 12] = e3;
            ls += __shfl_xor_sync(0xffffffffu, ls, 1);
            ls += __shfl_xor_sync(0xffffffffu, ls, 2);
            l_run = l_run * corr + ls;
            m_run = mnew;
            if (sc == 0) corr_sh[sq] = corr;
        }
        __syncthreads();

        // ---- PV accumulate (f32x2) ----
        {
            u64 cD = packdup(corr_sh[q]);
            acc[0] = mul2(acc[0], cD);
            acc[1] = mul2(acc[1], cD);
            acc[2] = mul2(acc[2], cD);
            acc[3] = mul2(acc[3], cD);
#pragma unroll 4
            for (int j = 0; j < 64; j += 4) {
                float4 p4 = *(const float4*)&Ss[q][j];
                u64 v0, v1, v2, v3, pD;
                pD = packdup(p4.x);
                lds2(v0, v1, &Vs[j + 0][d0]); lds2(v2, v3, &Vs[j + 0][d0 + 4]);
                fma2(acc[0], pD, v0); fma2(acc[1], pD, v1);
                fma2(acc[2], pD, v2); fma2(acc[3], pD, v3);
                pD = packdup(p4.y);
                lds2(v0, v1, &Vs[j + 1][d0]); lds2(v2, v3, &Vs[j + 1][d0 + 4]);
                fma2(acc[0], pD, v0); fma2(acc[1], pD, v1);
                fma2(acc[2], pD, v2); fma2(acc[3], pD, v3);
                pD = packdup(p4.z);
                lds2(v0, v1, &Vs[j + 2][d0]); lds2(v2, v3, &Vs[j + 2][d0 + 4]);
                fma2(acc[0], pD, v0); fma2(acc[1], pD, v1);
                fma2(acc[2], pD, v2); fma2(acc[3], pD, v3);
                pD = packdup(p4.w);
                lds2(v0, v1, &Vs[j + 3][d0]); lds2(v2, v3, &Vs[j + 3][d0 + 4]);
                fma2(acc[0], pD, v0); fma2(acc[1], pD, v1);
                fma2(acc[2], pD, v2); fma2(acc[3], pD, v3);
            }
        }
        __syncthreads();
    }

    if (sc == 0) lfin_sh[sq] = l_run;
    __syncthreads();

    if (qg < SEQ) {
        float inv = 1.f / lfin_sh[q];
        float o[8];
        unpack2(acc[0], o[0], o[1]);
        unpack2(acc[1], o[2], o[3]);
        unpack2(acc[2], o[4], o[5]);
        unpack2(acc[3], o[6], o[7]);
        float* outp = g_O + ((size_t)b * SEQ + qg) * CDIM + h * HD + d0;
        float4 w0 = make_float4(o[0]*inv, o[1]*inv, o[2]*inv, o[3]*inv);
        float4 w1 = make_float4(o[4]*inv, o[5]*inv, o[6]*inv, o[7]*inv);
        *(float4*)outp       = w0;
        *(float4*)(outp + 4) = w1;
    }
}

// ---------------------------------------------------------------------------
// Kernel 3: depthwise 5x5 LePE (NHWC, SAME), adds into g_O rows 1..3136.
// ---------------------------------------------------------------------------
__global__ __launch_bounds__(256) void lepe_kernel(
    const float* __restrict__ x, const float* __restrict__ w,
    const float* __restrict__ bias)
{
    __shared__ float ws[CDIM * 25];
    const int c = threadIdx.x;
    for (int idx = c; idx < CDIM * 25; idx += 256) ws[idx] = w[idx];
    __syncthreads();

    const int blk  = blockIdx.x;         // 0 .. 4*56*7-1
    const int b    = blk / (HW * 7);
    const int rem  = blk % (HW * 7);
    const int hh   = rem / 7;
    const int ww0  = (rem % 7) * 8;
    const float bc = bias[c];

#pragma unroll
    for (int p = 0; p < 8; p++) {
        int ww = ww0 + p;
        float sum = bc;
#pragma unroll
        for (int dy = 0; dy < 5; dy++) {
            int y = hh + dy - 2;
            if (y < 0 || y >= HW) continue;
#pragma unroll
            for (int dx = 0; dx < 5; dx++) {
                int xx = ww + dx - 2;
                if (xx < 0 || xx >= HW) continue;
                sum = fmaf(x[(((size_t)b * HW + y) * HW + xx) * CDIM + c],
                           ws[c * 25 + dy * 5 + dx], sum);
            }
        }
        int hw = hh * HW + ww;
        g_O[((size_t)b * SEQ + 1 + hw) * CDIM + c] += sum;
    }
}

// ---------------------------------------------------------------------------
// Kernel 4: proj GEMM (12548 x 256 x 256), packed f32x2, +bias, split output.
// ---------------------------------------------------------------------------
__global__ __launch_bounds__(256) void proj_gemm_kernel(
    const float* __restrict__ w, const float* __restrict__ bias,
    float* __restrict__ out)
{
    __shared__ float Ash[16][64];
    __shared__ float Wsh[16][64];

    const int t  = threadIdx.x;
    const int tx = t & 15;
    const int ty = t >> 4;
    const int rowBase = blockIdx.x * 64;
    const int colBase = blockIdx.y * 64;

    const int lm = t >> 2;
    const int lk = (t & 3) * 4;

    const float* arow = (rowBase + lm < MTOT)
                      ? (g_O + (size_t)(rowBase + lm) * CDIM) : nullptr;
    const float* wrow = w + (size_t)(colBase + lm) * CDIM;

    u64 accp[4][2] = {};

    for (int k0 = 0; k0 < CDIM; k0 += 16) {
        float4 av = arow ? *(const float4*)(arow + k0 + lk)
                         : make_float4(0.f, 0.f, 0.f, 0.f);
        float4 wv = *(const float4*)(wrow + k0 + lk);
        __syncthreads();
        Ash[lk + 0][lm] = av.x; Ash[lk + 1][lm] = av.y;
        Ash[lk + 2][lm] = av.z; Ash[lk + 3][lm] = av.w;
        Wsh[lk + 0][lm] = wv.x; Wsh[lk + 1][lm] = wv.y;
        Wsh[lk + 2][lm] = wv.z; Wsh[lk + 3][lm] = wv.w;
        __syncthreads();
#pragma unroll
        for (int kk = 0; kk < 16; kk++) {
            float4 a4 = *(const float4*)&Ash[kk][ty * 4];
            u64 w01, w23; lds2(w01, w23, &Wsh[kk][tx * 4]);
            u64 aD;
            aD = packdup(a4.x); fma2(accp[0][0], aD, w01); fma2(accp[0][1], aD, w23);
            aD = packdup(a4.y); fma2(accp[1][0], aD, w01); fma2(accp[1][1], aD, w23);
            aD = packdup(a4.z); fma2(accp[2][0], aD, w01); fma2(accp[2][1], aD, w23);
            aD = packdup(a4.w); fma2(accp[3][0], aD, w01); fma2(accp[3][1], aD, w23);
        }
    }

    const size_t cls_off = (size_t)BATCH * NPIX * CDIM;
#pragma unroll
    for (int i = 0; i < 4; i++) {
        int r = rowBase + ty * 4 + i;
        if (r >= MTOT) continue;
        int b = r / SEQ, s = r % SEQ;
        float vals[4];
        unpack2(accp[i][0], vals[0], vals[1]);
        unpack2(accp[i][1], vals[2], vals[3]);
#pragma unroll
        for (int j = 0; j < 4; j++) {
            int col = colBase + tx * 4 + j;
            float v = vals[j] + bias[col];
            size_t dst = (s == 0)
                       ? cls_off + (size_t)b * CDIM + col
                       : ((size_t)b * NPIX + (s - 1)) * CDIM + col;
            out[dst] = v;
        }
    }
}

// ---------------------------------------------------------------------------
extern "C" void kernel_launch(void* const* d_in, const int* in_sizes, int n_in,
                              void* d_out, int out_size)
{
    const float* x      = (const float*)d_in[0];
    const float* cls    = (const float*)d_in[1];
    const float* qkv_w  = (const float*)d_in[2];
    const float* proj_w = (const float*)d_in[3];
    const float* proj_b = (const float*)d_in[4];
    const float* lepe_w = (const float*)d_in[5];
    const float* lepe_b = (const float*)d_in[6];
    float* out = (float*)d_out;

    dim3 g1((MTOT + 63) / 64, QKV_N / 64);        // 197 x 12
    qkv_gemm_kernel<<<g1, 256>>>(x, cls, qkv_w);

    dim3 g2((SEQ + 63) / 64, HEADS, BATCH);       // 50 x 8 x 4
    flash_attn_kernel<<<g2, 256>>>();

    lepe_kernel<<<BATCH * HW * 7, 256>>>(x, lepe_w, lepe_b);

    dim3 g4((MTOT + 63) / 64, CDIM / 64);         // 197 x 4
    proj_gemm_kernel<<<g4, 256>>>(proj_w, proj_b, out);
}

// round 8
// speedup vs baseline: 2.0518x; 1.9321x over previous
#include <cuda_runtime.h>
#include <cstdint>

#define BATCH 4
#define HEADS 8
#define SEQ   3137          // 1 cls + 56*56
#define HD    32
#define CDIM  256
#define HW    56
#define NPIX  (HW*HW)       // 3136
#define MTOT  (BATCH*SEQ)   // 12548
#define QKV_N 768

typedef unsigned long long u64;

// ---------------- packed fp32x2 helpers (sm_100+ f32x2 pipe) ---------------
__device__ __forceinline__ u64 packdup(float x) {
    u64 r; asm("mov.b64 %0, {%1, %1};" : "=l"(r) : "f"(x)); return r;
}
__device__ __forceinline__ void fma2(u64 &d, u64 a, u64 b) {
    asm("fma.rn.f32x2 %0, %1, %2, %0;" : "+l"(d) : "l"(a), "l"(b));
}
__device__ __forceinline__ void unpack2(u64 v, float &x, float &y) {
    asm("mov.b64 {%0, %1}, %2;" : "=f"(x), "=f"(y) : "l"(v));
}
__device__ __forceinline__ void lds2(u64 &a, u64 &b, const void *p) {
    unsigned addr = (unsigned)__cvta_generic_to_shared(p);
    asm volatile("ld.shared.v2.u64 {%0, %1}, [%2];" : "=l"(a), "=l"(b) : "r"(addr));
}

// ---------------- tf32 mma helpers ----------------------------------------
__device__ __forceinline__ unsigned f2tf32(float x) {
    unsigned r; asm("cvt.rna.tf32.f32 %0, %1;" : "=r"(r) : "f"(x)); return r;
}
__device__ __forceinline__ void mma_tf32(float c[4], const unsigned a[4],
                                         unsigned b0, unsigned b1) {
    asm volatile(
        "mma.sync.aligned.m16n8k8.row.col.f32.tf32.tf32.f32 "
        "{%0,%1,%2,%3}, {%4,%5,%6,%7}, {%8,%9}, {%0,%1,%2,%3};"
        : "+f"(c[0]), "+f"(c[1]), "+f"(c[2]), "+f"(c[3])
        : "r"(a[0]), "r"(a[1]), "r"(a[2]), "r"(a[3]), "r"(b0), "r"(b1));
}

// ---------------- scratch (device globals; no allocation allowed) ----------
__device__ float g_Q[(size_t)BATCH*HEADS*SEQ*HD];
__device__ float g_K[(size_t)BATCH*HEADS*SEQ*HD];
__device__ float g_V[(size_t)BATCH*HEADS*SEQ*HD];
__device__ float g_O[(size_t)BATCH*SEQ*CDIM];

// ---------------------------------------------------------------------------
// Kernel 1: QKV GEMM (M=12548, N=768, K=256), packed f32x2 micro-kernel.
// Scatter into g_Q/g_K/g_V with layout (b, head, s, d); Q pre-scaled.
// ---------------------------------------------------------------------------
__global__ __launch_bounds__(256) void qkv_gemm_kernel(
    const float* __restrict__ x, const float* __restrict__ cls,
    const float* __restrict__ w)
{
    __shared__ float Ash[16][64];
    __shared__ float Wsh[16][64];

    const int t  = threadIdx.x;
    const int tx = t & 15;
    const int ty = t >> 4;
    const int rowBase = blockIdx.x * 64;
    const int colBase = blockIdx.y * 64;

    const int lm = t >> 2;
    const int lk = (t & 3) * 4;

    const float* arow = nullptr;
    {
        int gr = rowBase + lm;
        if (gr < MTOT) {
            int b = gr / SEQ, s = gr % SEQ;
            arow = (s == 0) ? (cls + (size_t)b * CDIM)
                            : (x + ((size_t)b * NPIX + (s - 1)) * CDIM);
        }
    }
    const float* wrow = w + (size_t)(colBase + lm) * CDIM;

    u64 accp[4][2] = {};

    for (int k0 = 0; k0 < CDIM; k0 += 16) {
        float4 av = arow ? *(const float4*)(arow + k0 + lk)
                         : make_float4(0.f, 0.f, 0.f, 0.f);
        float4 wv = *(const float4*)(wrow + k0 + lk);
        __syncthreads();
        Ash[lk + 0][lm] = av.x; Ash[lk + 1][lm] = av.y;
        Ash[lk + 2][lm] = av.z; Ash[lk + 3][lm] = av.w;
        Wsh[lk + 0][lm] = wv.x; Wsh[lk + 1][lm] = wv.y;
        Wsh[lk + 2][lm] = wv.z; Wsh[lk + 3][lm] = wv.w;
        __syncthreads();
#pragma unroll
        for (int kk = 0; kk < 16; kk++) {
            float4 a4 = *(const float4*)&Ash[kk][ty * 4];
            u64 w01, w23; lds2(w01, w23, &Wsh[kk][tx * 4]);
            u64 aD;
            aD = packdup(a4.x); fma2(accp[0][0], aD, w01); fma2(accp[0][1], aD, w23);
            aD = packdup(a4.y); fma2(accp[1][0], aD, w01); fma2(accp[1][1], aD, w23);
            aD = packdup(a4.z); fma2(accp[2][0], aD, w01); fma2(accp[2][1], aD, w23);
            aD = packdup(a4.w); fma2(accp[3][0], aD, w01); fma2(accp[3][1], aD, w23);
        }
    }

    const float scale = 0.17677669529663689f;  // 32^-0.5
#pragma unroll
    for (int i = 0; i < 4; i++) {
        int r = rowBase + ty * 4 + i;
        if (r >= MTOT) continue;
        int b = r / SEQ, s = r % SEQ;
        float vals[4];
        unpack2(accp[i][0], vals[0], vals[1]);
        unpack2(accp[i][1], vals[2], vals[3]);
#pragma unroll
        for (int j = 0; j < 4; j++) {
            int col   = colBase + tx * 4 + j;
            int which = col >> 8;
            int f     = col & 255;
            int head  = f >> 5;
            int d     = f & 31;
            size_t dst = (((size_t)(b * HEADS + head)) * SEQ + s) * HD + d;
            float v = vals[j];
            if (which == 0)      g_Q[dst] = v * scale;
            else if (which == 1) g_K[dst] = v;
            else                 g_V[dst] = v;
        }
    }
}

// ---------------------------------------------------------------------------
// Kernel 2: flash attention on tensor cores (mma.sync tf32, 3xTF32 accuracy).
// Block = 256 thr (8 warps), tile = 128 queries x 64-key chunks.
// Each warp: m16 (16 queries), scores kept in registers, softmax via quad
// shuffles, P->A-fragment via shuffles, K/V staged in smem pre-split into
// big/small tf32 tiles (decomposition done once per element).
// ---------------------------------------------------------------------------
#define KSTRIDE 36
#define VSTRIDE 40

__global__ __launch_bounds__(256) void flash_attn_tc_kernel()
{
    const int b  = blockIdx.z;
    const int h  = blockIdx.y;
    const int qt = blockIdx.x;

    const float* Qg = g_Q + ((size_t)(b * HEADS + h)) * SEQ * HD;
    const float* Kg = g_K + ((size_t)(b * HEADS + h)) * SEQ * HD;
    const float* Vg = g_V + ((size_t)(b * HEADS + h)) * SEQ * HD;

    __shared__ float KbigS[64 * KSTRIDE];
    __shared__ float KsmS [64 * KSTRIDE];
    __shared__ float VbigS[64 * VSTRIDE];
    __shared__ float VsmS [64 * VSTRIDE];

    const int t    = threadIdx.x;
    const int warp = t >> 5;
    const int lane = t & 31;
    const int g    = lane >> 2;   // group (row within fragment)
    const int tq   = lane & 3;    // thread-in-group (col)

    const int qbase = qt * 128 + warp * 16;

    // ---- resident Q fragments (big/small tf32), loaded once from gmem ----
    unsigned qb[4][4], qs[4][4];
    {
        int r0 = qbase + g;     if (r0 > SEQ - 1) r0 = SEQ - 1;
        int r1 = qbase + g + 8; if (r1 > SEQ - 1) r1 = SEQ - 1;
#pragma unroll
        for (int kc = 0; kc < 4; kc++) {
            int c0 = kc * 8 + tq, c1 = c0 + 4;
            float v[4];
            v[0] = Qg[(size_t)r0 * HD + c0];
            v[1] = Qg[(size_t)r1 * HD + c0];
            v[2] = Qg[(size_t)r0 * HD + c1];
            v[3] = Qg[(size_t)r1 * HD + c1];
#pragma unroll
            for (int i = 0; i < 4; i++) {
                qb[kc][i] = f2tf32(v[i]);
                qs[kc][i] = f2tf32(v[i] - __uint_as_float(qb[kc][i]));
            }
        }
    }

    float O[4][4] = {};                 // 16q x 32d output fragments
    float m0 = -1e30f, m1 = -1e30f;
    float l0 = 0.f, l1 = 0.f;

    const int NKT = (SEQ + 63) / 64;    // 50
    for (int kt = 0; kt < NKT; kt++) {
        const int kbase = kt * 64;

        __syncthreads();
        // ---- stage K/V chunk, pre-decomposed into big/small tf32 tiles ----
#pragma unroll
        for (int i = 0; i < 2; i++) {
            int idx = t * 2 + i;            // 0..511 float4s
            int row = idx >> 3;
            int c4  = (idx & 7) * 4;
            int krow = kbase + row; if (krow > SEQ - 1) krow = SEQ - 1;
            float4 kv = *(const float4*)(Kg + (size_t)krow * HD + c4);
            float4 vv = *(const float4*)(Vg + (size_t)krow * HD + c4);
            float kin[4] = {kv.x, kv.y, kv.z, kv.w};
            float vin[4] = {vv.x, vv.y, vv.z, vv.w};
            float kb4[4], ks4[4], vb4[4], vs4[4];
#pragma unroll
            for (int e = 0; e < 4; e++) {
                unsigned bb = f2tf32(kin[e]);
                kb4[e] = __uint_as_float(bb);
                ks4[e] = __uint_as_float(f2tf32(kin[e] - kb4[e]));
                unsigned vb = f2tf32(vin[e]);
                vb4[e] = __uint_as_float(vb);
                vs4[e] = __uint_as_float(f2tf32(vin[e] - vb4[e]));
            }
            *(float4*)&KbigS[row * KSTRIDE + c4] = make_float4(kb4[0],kb4[1],kb4[2],kb4[3]);
            *(float4*)&KsmS [row * KSTRIDE + c4] = make_float4(ks4[0],ks4[1],ks4[2],ks4[3]);
            *(float4*)&VbigS[row * VSTRIDE + c4] = make_float4(vb4[0],vb4[1],vb4[2],vb4[3]);
            *(float4*)&VsmS [row * VSTRIDE + c4] = make_float4(vs4[0],vs4[1],vs4[2],vs4[3]);
        }
        __syncthreads();

        // ---- S = Q K^T : 8 n-tiles of 8 keys, 3-pass tf32 ----
        float s[8][4];
#pragma unroll
        for (int nt = 0; nt < 8; nt++) {
            s[nt][0] = 0.f; s[nt][1] = 0.f; s[nt][2] = 0.f; s[nt][3] = 0.f;
#pragma unroll
            for (int kc = 0; kc < 4; kc++) {
                int kr = (nt * 8 + g) * KSTRIDE + kc * 8 + tq;
                unsigned kb0 = __float_as_uint(KbigS[kr]);
                unsigned kb1 = __float_as_uint(KbigS[kr + 4]);
                unsigned ks0 = __float_as_uint(KsmS[kr]);
                unsigned ks1 = __float_as_uint(KsmS[kr + 4]);
                mma_tf32(s[nt], qb[kc], kb0, kb1);
                mma_tf32(s[nt], qs[kc], kb0, kb1);
                mma_tf32(s[nt], qb[kc], ks0, ks1);
            }
        }

        // ---- mask invalid keys (only last chunk) ----
        if (kbase + 64 > SEQ) {
#pragma unroll
            for (int nt = 0; nt < 8; nt++) {
                int c = kbase + nt * 8 + 2 * tq;
                if (c     >= SEQ) { s[nt][0] = -1e30f; s[nt][2] = -1e30f; }
                if (c + 1 >= SEQ) { s[nt][1] = -1e30f; s[nt][3] = -1e30f; }
            }
        }

        // ---- online softmax (rows g and g+8), quad shuffles ----
        float mx0 = -1e30f, mx1 = -1e30f;
#pragma unroll
        for (int nt = 0; nt < 8; nt++) {
            mx0 = fmaxf(mx0, fmaxf(s[nt][0], s[nt][1]));
            mx1 = fmaxf(mx1, fmaxf(s[nt][2], s[nt][3]));
        }
        mx0 = fmaxf(mx0, __shfl_xor_sync(0xffffffffu, mx0, 1));
        mx0 = fmaxf(mx0, __shfl_xor_sync(0xffffffffu, mx0, 2));
        mx1 = fmaxf(mx1, __shfl_xor_sync(0xffffffffu, mx1, 1));
        mx1 = fmaxf(mx1, __shfl_xor_sync(0xffffffffu, mx1, 2));
        float mn0 = fmaxf(m0, mx0), mn1 = fmaxf(m1, mx1);
        float corr0 = __expf(m0 - mn0), corr1 = __expf(m1 - mn1);

        float ls0 = 0.f, ls1 = 0.f;
#pragma unroll
        for (int nt = 0; nt < 8; nt++) {
            s[nt][0] = __expf(s[nt][0] - mn0);
            s[nt][1] = __expf(s[nt][1] - mn0);
            s[nt][2] = __expf(s[nt][2] - mn1);
            s[nt][3] = __expf(s[nt][3] - mn1);
            ls0 += s[nt][0] + s[nt][1];
            ls1 += s[nt][2] + s[nt][3];
        }
        ls0 += __shfl_xor_sync(0xffffffffu, ls0, 1);
        ls0 += __shfl_xor_sync(0xffffffffu, ls0, 2);
        ls1 += __shfl_xor_sync(0xffffffffu, ls1, 1);
        ls1 += __shfl_xor_sync(0xffffffffu, ls1, 2);
        l0 = l0 * corr0 + ls0;  m0 = mn0;
        l1 = l1 * corr1 + ls1;  m1 = mn1;

#pragma unroll
        for (int nt = 0; nt < 4; nt++) {
            O[nt][0] *= corr0; O[nt][1] *= corr0;
            O[nt][2] *= corr1; O[nt][3] *= corr1;
        }

        // ---- O += P V : re-fragment P via shuffles, 3-pass tf32 ----
        const int src0 = (lane & ~3) | (tq >> 1);
        const int src1 = src0 + 2;
        const bool odd = (tq & 1);
#pragma unroll
        for (int kc = 0; kc < 8; kc++) {
            float q0e = __shfl_sync(0xffffffffu, s[kc][0], src0);
            float q0o = __shfl_sync(0xffffffffu, s[kc][1], src0);
            float q2e = __shfl_sync(0xffffffffu, s[kc][0], src1);
            float q2o = __shfl_sync(0xffffffffu, s[kc][1], src1);
            float q1e = __shfl_sync(0xffffffffu, s[kc][2], src0);
            float q1o = __shfl_sync(0xffffffffu, s[kc][3], src0);
            float q3e = __shfl_sync(0xffffffffu, s[kc][2], src1);
            float q3o = __shfl_sync(0xffffffffu, s[kc][3], src1);
            float p[4];
            p[0] = odd ? q0o : q0e;   // row g,   key kc*8+tq
            p[1] = odd ? q1o : q1e;   // row g+8, key kc*8+tq
            p[2] = odd ? q2o : q2e;   // row g,   key kc*8+tq+4
            p[3] = odd ? q3o : q3e;   // row g+8, key kc*8+tq+4
            unsigned pb[4], ps[4];
#pragma unroll
            for (int i = 0; i < 4; i++) {
                pb[i] = f2tf32(p[i]);
                ps[i] = f2tf32(p[i] - __uint_as_float(pb[i]));
            }
            int vr0 = (kc * 8 + tq) * VSTRIDE;
            int vr1 = (kc * 8 + tq + 4) * VSTRIDE;
#pragma unroll
            for (int nt = 0; nt < 4; nt++) {
                int colv = nt * 8 + g;
                unsigned vb0 = __float_as_uint(VbigS[vr0 + colv]);
                unsigned vb1 = __float_as_uint(VbigS[vr1 + colv]);
                unsigned vs0 = __float_as_uint(VsmS[vr0 + colv]);
                unsigned vs1 = __float_as_uint(VsmS[vr1 + colv]);
                mma_tf32(O[nt], pb, vb0, vb1);
                mma_tf32(O[nt], ps, vb0, vb1);
                mma_tf32(O[nt], pb, vs0, vs1);
            }
        }
    }

    // ---- epilogue ----
    float inv0 = 1.f / l0, inv1 = 1.f / l1;
    int r0 = qbase + g;
    int r1 = qbase + g + 8;
#pragma unroll
    for (int nt = 0; nt < 4; nt++) {
        int col = h * HD + nt * 8 + 2 * tq;
        if (r0 < SEQ) {
            float2 v = make_float2(O[nt][0] * inv0, O[nt][1] * inv0);
            *(float2*)&g_O[((size_t)b * SEQ + r0) * CDIM + col] = v;
        }
        if (r1 < SEQ) {
            float2 v = make_float2(O[nt][2] * inv1, O[nt][3] * inv1);
            *(float2*)&g_O[((size_t)b * SEQ + r1) * CDIM + col] = v;
        }
    }
}

// ---------------------------------------------------------------------------
// Kernel 3: depthwise 5x5 LePE (NHWC, SAME), adds into g_O rows 1..3136.
// ---------------------------------------------------------------------------
__global__ __launch_bounds__(256) void lepe_kernel(
    const float* __restrict__ x, const float* __restrict__ w,
    const float* __restrict__ bias)
{
    __shared__ float ws[CDIM * 25];
    const int c = threadIdx.x;
    for (int idx = c; idx < CDIM * 25; idx += 256) ws[idx] = w[idx];
    __syncthreads();

    const int blk  = blockIdx.x;         // 0 .. 4*56*7-1
    const int b    = blk / (HW * 7);
    const int rem  = blk % (HW * 7);
    const int hh   = rem / 7;
    const int ww0  = (rem % 7) * 8;
    const float bc = bias[c];

#pragma unroll
    for (int p = 0; p < 8; p++) {
        int ww = ww0 + p;
        float sum = bc;
#pragma unroll
        for (int dy = 0; dy < 5; dy++) {
            int y = hh + dy - 2;
            if (y < 0 || y >= HW) continue;
#pragma unroll
            for (int dx = 0; dx < 5; dx++) {
                int xx = ww + dx - 2;
                if (xx < 0 || xx >= HW) continue;
                sum = fmaf(x[(((size_t)b * HW + y) * HW + xx) * CDIM + c],
                           ws[c * 25 + dy * 5 + dx], sum);
            }
        }
        int hw = hh * HW + ww;
        g_O[((size_t)b * SEQ + 1 + hw) * CDIM + c] += sum;
    }
}

// ---------------------------------------------------------------------------
// Kernel 4: proj GEMM (12548 x 256 x 256), packed f32x2, +bias, split output.
// ---------------------------------------------------------------------------
__global__ __launch_bounds__(256) void proj_gemm_kernel(
    const float* __restrict__ w, const float* __restrict__ bias,
    float* __restrict__ out)
{
    __shared__ float Ash[16][64];
    __shared__ float Wsh[16][64];

    const int t  = threadIdx.x;
    const int tx = t & 15;
    const int ty = t >> 4;
    const int rowBase = blockIdx.x * 64;
    const int colBase = blockIdx.y * 64;

    const int lm = t >> 2;
    const int lk = (t & 3) * 4;

    const float* arow = (rowBase + lm < MTOT)
                      ? (g_O + (size_t)(rowBase + lm) * CDIM) : nullptr;
    const float* wrow = w + (size_t)(colBase + lm) * CDIM;

    u64 accp[4][2] = {};

    for (int k0 = 0; k0 < CDIM; k0 += 16) {
        float4 av = arow ? *(const float4*)(arow + k0 + lk)
                         : make_float4(0.f, 0.f, 0.f, 0.f);
        float4 wv = *(const float4*)(wrow + k0 + lk);
        __syncthreads();
        Ash[lk + 0][lm] = av.x; Ash[lk + 1][lm] = av.y;
        Ash[lk + 2][lm] = av.z; Ash[lk + 3][lm] = av.w;
        Wsh[lk + 0][lm] = wv.x; Wsh[lk + 1][lm] = wv.y;
        Wsh[lk + 2][lm] = wv.z; Wsh[lk + 3][lm] = wv.w;
        __syncthreads();
#pragma unroll
        for (int kk = 0; kk < 16; kk++) {
            float4 a4 = *(const float4*)&Ash[kk][ty * 4];
            u64 w01, w23; lds2(w01, w23, &Wsh[kk][tx * 4]);
            u64 aD;
            aD = packdup(a4.x); fma2(accp[0][0], aD, w01); fma2(accp[0][1], aD, w23);
            aD = packdup(a4.y); fma2(accp[1][0], aD, w01); fma2(accp[1][1], aD, w23);
            aD = packdup(a4.z); fma2(accp[2][0], aD, w01); fma2(accp[2][1], aD, w23);
            aD = packdup(a4.w); fma2(accp[3][0], aD, w01); fma2(accp[3][1], aD, w23);
        }
    }

    const size_t cls_off = (size_t)BATCH * NPIX * CDIM;
#pragma unroll
    for (int i = 0; i < 4; i++) {
        int r = rowBase + ty * 4 + i;
        if (r >= MTOT) continue;
        int b = r / SEQ, s = r % SEQ;
        float vals[4];
        unpack2(accp[i][0], vals[0], vals[1]);
        unpack2(accp[i][1], vals[2], vals[3]);
#pragma unroll
        for (int j = 0; j < 4; j++) {
            int col = colBase + tx * 4 + j;
            float v = vals[j] + bias[col];
            size_t dst = (s == 0)
                       ? cls_off + (size_t)b * CDIM + col
                       : ((size_t)b * NPIX + (s - 1)) * CDIM + col;
            out[dst] = v;
        }
    }
}

// ---------------------------------------------------------------------------
extern "C" void kernel_launch(void* const* d_in, const int* in_sizes, int n_in,
                              void* d_out, int out_size)
{
    const float* x      = (const float*)d_in[0];
    const float* cls    = (const float*)d_in[1];
    const float* qkv_w  = (const float*)d_in[2];
    const float* proj_w = (const float*)d_in[3];
    const float* proj_b = (const float*)d_in[4];
    const float* lepe_w = (const float*)d_in[5];
    const float* lepe_b = (const float*)d_in[6];
    float* out = (float*)d_out;

    dim3 g1((MTOT + 63) / 64, QKV_N / 64);        // 197 x 12
    qkv_gemm_kernel<<<g1, 256>>>(x, cls, qkv_w);

    dim3 g2((SEQ + 127) / 128, HEADS, BATCH);     // 25 x 8 x 4
    flash_attn_tc_kernel<<<g2, 256>>>();

    lepe_kernel<<<BATCH * HW * 7, 256>>>(x, lepe_w, lepe_b);

    dim3 g4((MTOT + 63) / 64, CDIM / 64);         // 197 x 4
    proj_gemm_kernel<<<g4, 256>>>(proj_w, proj_b, out);
}

// round 9
// speedup vs baseline: 2.1683x; 1.0568x over previous
#include <cuda_runtime.h>
#include <cstdint>

#define BATCH 4
#define HEADS 8
#define SEQ   3137          // 1 cls + 56*56
#define HD    32
#define CDIM  256
#define HW    56
#define NPIX  (HW*HW)       // 3136
#define MTOT  (BATCH*SEQ)   // 12548
#define QKV_N 768

typedef unsigned long long u64;

// ---------------- packed fp32x2 helpers (sm_100+ f32x2 pipe) ---------------
__device__ __forceinline__ u64 packdup(float x) {
    u64 r; asm("mov.b64 %0, {%1, %1};" : "=l"(r) : "f"(x)); return r;
}
__device__ __forceinline__ void fma2(u64 &d, u64 a, u64 b) {
    asm("fma.rn.f32x2 %0, %1, %2, %0;" : "+l"(d) : "l"(a), "l"(b));
}
__device__ __forceinline__ void unpack2(u64 v, float &x, float &y) {
    asm("mov.b64 {%0, %1}, %2;" : "=f"(x), "=f"(y) : "l"(v));
}
__device__ __forceinline__ void lds2(u64 &a, u64 &b, const void *p) {
    unsigned addr = (unsigned)__cvta_generic_to_shared(p);
    asm volatile("ld.shared.v2.u64 {%0, %1}, [%2];" : "=l"(a), "=l"(b) : "r"(addr));
}

// ---------------- tf32 mma helpers ----------------------------------------
__device__ __forceinline__ unsigned f2tf32(float x) {
    unsigned r; asm("cvt.rna.tf32.f32 %0, %1;" : "=r"(r) : "f"(x)); return r;
}
__device__ __forceinline__ void mma_tf32(float c[4], const unsigned a[4],
                                         unsigned b0, unsigned b1) {
    asm volatile(
        "mma.sync.aligned.m16n8k8.row.col.f32.tf32.tf32.f32 "
        "{%0,%1,%2,%3}, {%4,%5,%6,%7}, {%8,%9}, {%0,%1,%2,%3};"
        : "+f"(c[0]), "+f"(c[1]), "+f"(c[2]), "+f"(c[3])
        : "r"(a[0]), "r"(a[1]), "r"(a[2]), "r"(a[3]), "r"(b0), "r"(b1));
}

// ---------------- scratch (device globals; no allocation allowed) ----------
__device__ float g_Q[(size_t)BATCH*HEADS*SEQ*HD];
__device__ float g_K[(size_t)BATCH*HEADS*SEQ*HD];
__device__ float g_V[(size_t)BATCH*HEADS*SEQ*HD];
__device__ float g_O[(size_t)BATCH*SEQ*CDIM];

// ---------------------------------------------------------------------------
// Kernel 1: QKV GEMM (M=12548, N=768, K=256), packed f32x2 micro-kernel.
// ---------------------------------------------------------------------------
__global__ __launch_bounds__(256) void qkv_gemm_kernel(
    const float* __restrict__ x, const float* __restrict__ cls,
    const float* __restrict__ w)
{
    __shared__ float Ash[16][64];
    __shared__ float Wsh[16][64];

    const int t  = threadIdx.x;
    const int tx = t & 15;
    const int ty = t >> 4;
    const int rowBase = blockIdx.x * 64;
    const int colBase = blockIdx.y * 64;

    const int lm = t >> 2;
    const int lk = (t & 3) * 4;

    const float* arow = nullptr;
    {
        int gr = rowBase + lm;
        if (gr < MTOT) {
            int b = gr / SEQ, s = gr % SEQ;
            arow = (s == 0) ? (cls + (size_t)b * CDIM)
                            : (x + ((size_t)b * NPIX + (s - 1)) * CDIM);
        }
    }
    const float* wrow = w + (size_t)(colBase + lm) * CDIM;

    u64 accp[4][2] = {};

    for (int k0 = 0; k0 < CDIM; k0 += 16) {
        float4 av = arow ? *(const float4*)(arow + k0 + lk)
                         : make_float4(0.f, 0.f, 0.f, 0.f);
        float4 wv = *(const float4*)(wrow + k0 + lk);
        __syncthreads();
        Ash[lk + 0][lm] = av.x; Ash[lk + 1][lm] = av.y;
        Ash[lk + 2][lm] = av.z; Ash[lk + 3][lm] = av.w;
        Wsh[lk + 0][lm] = wv.x; Wsh[lk + 1][lm] = wv.y;
        Wsh[lk + 2][lm] = wv.z; Wsh[lk + 3][lm] = wv.w;
        __syncthreads();
#pragma unroll
        for (int kk = 0; kk < 16; kk++) {
            float4 a4 = *(const float4*)&Ash[kk][ty * 4];
            u64 w01, w23; lds2(w01, w23, &Wsh[kk][tx * 4]);
            u64 aD;
            aD = packdup(a4.x); fma2(accp[0][0], aD, w01); fma2(accp[0][1], aD, w23);
            aD = packdup(a4.y); fma2(accp[1][0], aD, w01); fma2(accp[1][1], aD, w23);
            aD = packdup(a4.z); fma2(accp[2][0], aD, w01); fma2(accp[2][1], aD, w23);
            aD = packdup(a4.w); fma2(accp[3][0], aD, w01); fma2(accp[3][1], aD, w23);
        }
    }

    const float scale = 0.17677669529663689f;  // 32^-0.5
#pragma unroll
    for (int i = 0; i < 4; i++) {
        int r = rowBase + ty * 4 + i;
        if (r >= MTOT) continue;
        int b = r / SEQ, s = r % SEQ;
        float vals[4];
        unpack2(accp[i][0], vals[0], vals[1]);
        unpack2(accp[i][1], vals[2], vals[3]);
#pragma unroll
        for (int j = 0; j < 4; j++) {
            int col   = colBase + tx * 4 + j;
            int which = col >> 8;
            int f     = col & 255;
            int head  = f >> 5;
            int d     = f & 31;
            size_t dst = (((size_t)(b * HEADS + head)) * SEQ + s) * HD + d;
            float v = vals[j];
            if (which == 0)      g_Q[dst] = v * scale;
            else if (which == 1) g_K[dst] = v;
            else                 g_V[dst] = v;
        }
    }
}

// ---------------------------------------------------------------------------
// Kernel 2: flash attention, tensor cores (tf32 3-pass), m32 per warp,
// fragment-major packed smem (LDS.128), software-pipelined staging.
// Block = 256 thr (8 warps) = 256 queries; 64-key chunks.
// ---------------------------------------------------------------------------
__global__ __launch_bounds__(256, 1) void flash_attn_tc_kernel()
{
    const int b  = blockIdx.z;
    const int h  = blockIdx.y;
    const int qt = blockIdx.x;

    const float* Qg = g_Q + ((size_t)(b * HEADS + h)) * SEQ * HD;
    const float* Kg = g_K + ((size_t)(b * HEADS + h)) * SEQ * HD;
    const float* Vg = g_V + ((size_t)(b * HEADS + h)) * SEQ * HD;

    // fragment-major packed tiles: float4 {big0, big1, sm0, sm1} per lane
    __shared__ float KP[8 * 4 * 32 * 4];   // (nt,kc,lane) -> 16 KB
    __shared__ float VP[8 * 4 * 32 * 4];   // (kc,nt,lane) -> 16 KB

    const int t    = threadIdx.x;
    const int warp = t >> 5;
    const int lane = t & 31;
    const int g    = lane >> 2;
    const int tq   = lane & 3;

    const int qbase = qt * 256 + warp * 32;

    // ---- resident Q fragments, 2 row-halves (big/small tf32) ----
    unsigned qb[2][4][4], qs[2][4][4];
#pragma unroll
    for (int hb = 0; hb < 2; hb++) {
        int r0 = qbase + hb * 16 + g;     if (r0 > SEQ - 1) r0 = SEQ - 1;
        int r1 = qbase + hb * 16 + g + 8; if (r1 > SEQ - 1) r1 = SEQ - 1;
#pragma unroll
        for (int kc = 0; kc < 4; kc++) {
            int c0 = kc * 8 + tq;
            float v[4];
            v[0] = Qg[(size_t)r0 * HD + c0];
            v[1] = Qg[(size_t)r1 * HD + c0];
            v[2] = Qg[(size_t)r0 * HD + c0 + 4];
            v[3] = Qg[(size_t)r1 * HD + c0 + 4];
#pragma unroll
            for (int i = 0; i < 4; i++) {
                qb[hb][kc][i] = f2tf32(v[i]);
                qs[hb][kc][i] = f2tf32(v[i] - __uint_as_float(qb[hb][kc][i]));
            }
        }
    }

    float O[2][4][4] = {};
    float m_run[2][2] = {{-1e30f, -1e30f}, {-1e30f, -1e30f}};
    float l_run[2][2] = {{0.f, 0.f}, {0.f, 0.f}};

    const int NKT = (SEQ + 63) / 64;    // 50

    // ---- prologue: raw-load chunk 0 into registers ----
    float kst[8], vst[8];
    {
        int n = warp * 8 + g; if (n > SEQ - 1) n = SEQ - 1;
        const float* kr = Kg + (size_t)n * HD + tq;
#pragma unroll
        for (int j = 0; j < 8; j++) kst[j] = kr[4 * j];
        int k0 = warp * 8 + tq;     if (k0 > SEQ - 1) k0 = SEQ - 1;
        int k1 = warp * 8 + tq + 4; if (k1 > SEQ - 1) k1 = SEQ - 1;
        const float* v0p = Vg + (size_t)k0 * HD + g;
        const float* v1p = Vg + (size_t)k1 * HD + g;
#pragma unroll
        for (int nt = 0; nt < 4; nt++) {
            vst[nt]     = v0p[nt * 8];
            vst[4 + nt] = v1p[nt * 8];
        }
    }

    for (int kt = 0; kt < NKT; kt++) {
        const int kbase = kt * 64;

        __syncthreads();   // prior chunk's smem reads complete
        // ---- decompose + store staged registers (packed layout) ----
        {
            float kb[8], ks[8];
#pragma unroll
            for (int j = 0; j < 8; j++) {
                unsigned bb = f2tf32(kst[j]);
                kb[j] = __uint_as_float(bb);
                ks[j] = __uint_as_float(f2tf32(kst[j] - kb[j]));
            }
#pragma unroll
            for (int kc = 0; kc < 4; kc++)
                *(float4*)&KP[(((warp * 4 + kc) * 32) + lane) * 4] =
                    make_float4(kb[2 * kc], kb[2 * kc + 1], ks[2 * kc], ks[2 * kc + 1]);
            float vb[8], vs[8];
#pragma unroll
            for (int j = 0; j < 8; j++) {
                unsigned bb = f2tf32(vst[j]);
                vb[j] = __uint_as_float(bb);
                vs[j] = __uint_as_float(f2tf32(vst[j] - vb[j]));
            }
#pragma unroll
            for (int nt = 0; nt < 4; nt++)
                *(float4*)&VP[(((warp * 4 + nt) * 32) + lane) * 4] =
                    make_float4(vb[nt], vb[4 + nt], vs[nt], vs[4 + nt]);
        }
        __syncthreads();

        // ---- prefetch raw chunk kt+1 (overlaps with compute below) ----
        if (kt + 1 < NKT) {
            int nb = (kt + 1) * 64;
            int n = nb + warp * 8 + g; if (n > SEQ - 1) n = SEQ - 1;
            const float* kr = Kg + (size_t)n * HD + tq;
#pragma unroll
            for (int j = 0; j < 8; j++) kst[j] = kr[4 * j];
            int k0 = nb + warp * 8 + tq;     if (k0 > SEQ - 1) k0 = SEQ - 1;
            int k1 = nb + warp * 8 + tq + 4; if (k1 > SEQ - 1) k1 = SEQ - 1;
            const float* v0p = Vg + (size_t)k0 * HD + g;
            const float* v1p = Vg + (size_t)k1 * HD + g;
#pragma unroll
            for (int nt = 0; nt < 4; nt++) {
                vst[nt]     = v0p[nt * 8];
                vst[4 + nt] = v1p[nt * 8];
            }
        }

        // ---- S = Q K^T : both halves share each K fragment ----
        float s[2][8][4];
#pragma unroll
        for (int nt = 0; nt < 8; nt++) {
#pragma unroll
            for (int hb = 0; hb < 2; hb++) {
                s[hb][nt][0] = 0.f; s[hb][nt][1] = 0.f;
                s[hb][nt][2] = 0.f; s[hb][nt][3] = 0.f;
            }
#pragma unroll
            for (int kc = 0; kc < 4; kc++) {
                float4 kf = *(const float4*)&KP[(((nt * 4 + kc) * 32) + lane) * 4];
                unsigned kb0 = __float_as_uint(kf.x), kb1 = __float_as_uint(kf.y);
                unsigned ks0 = __float_as_uint(kf.z), ks1 = __float_as_uint(kf.w);
#pragma unroll
                for (int hb = 0; hb < 2; hb++) {
                    mma_tf32(s[hb][nt], qb[hb][kc], kb0, kb1);
                    mma_tf32(s[hb][nt], qs[hb][kc], kb0, kb1);
                    mma_tf32(s[hb][nt], qb[hb][kc], ks0, ks1);
                }
            }
        }

        // ---- mask invalid keys (only last chunk) ----
        if (kbase + 64 > SEQ) {
#pragma unroll
            for (int nt = 0; nt < 8; nt++) {
                int c = kbase + nt * 8 + 2 * tq;
#pragma unroll
                for (int hb = 0; hb < 2; hb++) {
                    if (c     >= SEQ) { s[hb][nt][0] = -1e30f; s[hb][nt][2] = -1e30f; }
                    if (c + 1 >= SEQ) { s[hb][nt][1] = -1e30f; s[hb][nt][3] = -1e30f; }
                }
            }
        }

        // ---- online softmax per half ----
        float corr[2][2];
#pragma unroll
        for (int hb = 0; hb < 2; hb++) {
            float mx0 = -1e30f, mx1 = -1e30f;
#pragma unroll
            for (int nt = 0; nt < 8; nt++) {
                mx0 = fmaxf(mx0, fmaxf(s[hb][nt][0], s[hb][nt][1]));
                mx1 = fmaxf(mx1, fmaxf(s[hb][nt][2], s[hb][nt][3]));
            }
            mx0 = fmaxf(mx0, __shfl_xor_sync(0xffffffffu, mx0, 1));
            mx0 = fmaxf(mx0, __shfl_xor_sync(0xffffffffu, mx0, 2));
            mx1 = fmaxf(mx1, __shfl_xor_sync(0xffffffffu, mx1, 1));
            mx1 = fmaxf(mx1, __shfl_xor_sync(0xffffffffu, mx1, 2));
            float mn0 = fmaxf(m_run[hb][0], mx0);
            float mn1 = fmaxf(m_run[hb][1], mx1);
            corr[hb][0] = __expf(m_run[hb][0] - mn0);
            corr[hb][1] = __expf(m_run[hb][1] - mn1);

            float ls0 = 0.f, ls1 = 0.f;
#pragma unroll
            for (int nt = 0; nt < 8; nt++) {
                s[hb][nt][0] = __expf(s[hb][nt][0] - mn0);
                s[hb][nt][1] = __expf(s[hb][nt][1] - mn0);
                s[hb][nt][2] = __expf(s[hb][nt][2] - mn1);
                s[hb][nt][3] = __expf(s[hb][nt][3] - mn1);
                ls0 += s[hb][nt][0] + s[hb][nt][1];
                ls1 += s[hb][nt][2] + s[hb][nt][3];
            }
            ls0 += __shfl_xor_sync(0xffffffffu, ls0, 1);
            ls0 += __shfl_xor_sync(0xffffffffu, ls0, 2);
            ls1 += __shfl_xor_sync(0xffffffffu, ls1, 1);
            ls1 += __shfl_xor_sync(0xffffffffu, ls1, 2);
            l_run[hb][0] = l_run[hb][0] * corr[hb][0] + ls0;  m_run[hb][0] = mn0;
            l_run[hb][1] = l_run[hb][1] * corr[hb][1] + ls1;  m_run[hb][1] = mn1;

#pragma unroll
            for (int nt = 0; nt < 4; nt++) {
                O[hb][nt][0] *= corr[hb][0]; O[hb][nt][1] *= corr[hb][0];
                O[hb][nt][2] *= corr[hb][1]; O[hb][nt][3] *= corr[hb][1];
            }
        }

        // ---- O += P V : both halves share each V fragment ----
        const int src0 = (lane & ~3) | (tq >> 1);
        const int src1 = src0 + 2;
        const bool odd = (tq & 1);
#pragma unroll
        for (int kc = 0; kc < 8; kc++) {
            unsigned pb[2][4], ps[2][4];
#pragma unroll
            for (int hb = 0; hb < 2; hb++) {
                float q0e = __shfl_sync(0xffffffffu, s[hb][kc][0], src0);
                float q0o = __shfl_sync(0xffffffffu, s[hb][kc][1], src0);
                float q2e = __shfl_sync(0xffffffffu, s[hb][kc][0], src1);
                float q2o = __shfl_sync(0xffffffffu, s[hb][kc][1], src1);
                float q1e = __shfl_sync(0xffffffffu, s[hb][kc][2], src0);
                float q1o = __shfl_sync(0xffffffffu, s[hb][kc][3], src0);
                float q3e = __shfl_sync(0xffffffffu, s[hb][kc][2], src1);
                float q3o = __shfl_sync(0xffffffffu, s[hb][kc][3], src1);
                float p[4];
                p[0] = odd ? q0o : q0e;
                p[1] = odd ? q1o : q1e;
                p[2] = odd ? q2o : q2e;
                p[3] = odd ? q3o : q3e;
#pragma unroll
                for (int i = 0; i < 4; i++) {
                    pb[hb][i] = f2tf32(p[i]);
                    ps[hb][i] = f2tf32(p[i] - __uint_as_float(pb[hb][i]));
                }
            }
#pragma unroll
            for (int nt = 0; nt < 4; nt++) {
                float4 vf = *(const float4*)&VP[(((kc * 4 + nt) * 32) + lane) * 4];
                unsigned vb0 = __float_as_uint(vf.x), vb1 = __float_as_uint(vf.y);
                unsigned vs0 = __float_as_uint(vf.z), vs1 = __float_as_uint(vf.w);
#pragma unroll
                for (int hb = 0; hb < 2; hb++) {
                    mma_tf32(O[hb][nt], pb[hb], vb0, vb1);
                    mma_tf32(O[hb][nt], ps[hb], vb0, vb1);
                    mma_tf32(O[hb][nt], pb[hb], vs0, vs1);
                }
            }
        }
    }

    // ---- epilogue ----
#pragma unroll
    for (int hb = 0; hb < 2; hb++) {
        float inv0 = 1.f / l_run[hb][0], inv1 = 1.f / l_run[hb][1];
        int r0 = qbase + hb * 16 + g;
        int r1 = qbase + hb * 16 + g + 8;
#pragma unroll
        for (int nt = 0; nt < 4; nt++) {
            int col = h * HD + nt * 8 + 2 * tq;
            if (r0 < SEQ) {
                float2 v = make_float2(O[hb][nt][0] * inv0, O[hb][nt][1] * inv0);
                *(float2*)&g_O[((size_t)b * SEQ + r0) * CDIM + col] = v;
            }
            if (r1 < SEQ) {
                float2 v = make_float2(O[hb][nt][2] * inv1, O[hb][nt][3] * inv1);
                *(float2*)&g_O[((size_t)b * SEQ + r1) * CDIM + col] = v;
            }
        }
    }
}

// ---------------------------------------------------------------------------
// Kernel 3: depthwise 5x5 LePE (NHWC, SAME), adds into g_O rows 1..3136.
// ---------------------------------------------------------------------------
__global__ __launch_bounds__(256) void lepe_kernel(
    const float* __restrict__ x, const float* __restrict__ w,
    const float* __restrict__ bias)
{
    __shared__ float ws[CDIM * 25];
    const int c = threadIdx.x;
    for (int idx = c; idx < CDIM * 25; idx += 256) ws[idx] = w[idx];
    __syncthreads();

    const int blk  = blockIdx.x;         // 0 .. 4*56*7-1
    const int b    = blk / (HW * 7);
    const int rem  = blk % (HW * 7);
    const int hh   = rem / 7;
    const int ww0  = (rem % 7) * 8;
    const float bc = bias[c];

#pragma unroll
    for (int p = 0; p < 8; p++) {
        int ww = ww0 + p;
        float sum = bc;
#pragma unroll
        for (int dy = 0; dy < 5; dy++) {
            int y = hh + dy - 2;
            if (y < 0 || y >= HW) continue;
#pragma unroll
            for (int dx = 0; dx < 5; dx++) {
                int xx = ww + dx - 2;
                if (xx < 0 || xx >= HW) continue;
                sum = fmaf(x[(((size_t)b * HW + y) * HW + xx) * CDIM + c],
                           ws[c * 25 + dy * 5 + dx], sum);
            }
        }
        int hw = hh * HW + ww;
        g_O[((size_t)b * SEQ + 1 + hw) * CDIM + c] += sum;
    }
}

// ---------------------------------------------------------------------------
// Kernel 4: proj GEMM (12548 x 256 x 256), packed f32x2, +bias, split output.
// ---------------------------------------------------------------------------
__global__ __launch_bounds__(256) void proj_gemm_kernel(
    const float* __restrict__ w, const float* __restrict__ bias,
    float* __restrict__ out)
{
    __shared__ float Ash[16][64];
    __shared__ float Wsh[16][64];

    const int t  = threadIdx.x;
    const int tx = t & 15;
    const int ty = t >> 4;
    const int rowBase = blockIdx.x * 64;
    const int colBase = blockIdx.y * 64;

    const int lm = t >> 2;
    const int lk = (t & 3) * 4;

    const float* arow = (rowBase + lm < MTOT)
                      ? (g_O + (size_t)(rowBase + lm) * CDIM) : nullptr;
    const float* wrow = w + (size_t)(colBase + lm) * CDIM;

    u64 accp[4][2] = {};

    for (int k0 = 0; k0 < CDIM; k0 += 16) {
        float4 av = arow ? *(const float4*)(arow + k0 + lk)
                         : make_float4(0.f, 0.f, 0.f, 0.f);
        float4 wv = *(const float4*)(wrow + k0 + lk);
        __syncthreads();
        Ash[lk + 0][lm] = av.x; Ash[lk + 1][lm] = av.y;
        Ash[lk + 2][lm] = av.z; Ash[lk + 3][lm] = av.w;
        Wsh[lk + 0][lm] = wv.x; Wsh[lk + 1][lm] = wv.y;
        Wsh[lk + 2][lm] = wv.z; Wsh[lk + 3][lm] = wv.w;
        __syncthreads();
#pragma unroll
        for (int kk = 0; kk < 16; kk++) {
            float4 a4 = *(const float4*)&Ash[kk][ty * 4];
            u64 w01, w23; lds2(w01, w23, &Wsh[kk][tx * 4]);
            u64 aD;
            aD = packdup(a4.x); fma2(accp[0][0], aD, w01); fma2(accp[0][1], aD, w23);
            aD = packdup(a4.y); fma2(accp[1][0], aD, w01); fma2(accp[1][1], aD, w23);
            aD = packdup(a4.z); fma2(accp[2][0], aD, w01); fma2(accp[2][1], aD, w23);
            aD = packdup(a4.w); fma2(accp[3][0], aD, w01); fma2(accp[3][1], aD, w23);
        }
    }

    const size_t cls_off = (size_t)BATCH * NPIX * CDIM;
#pragma unroll
    for (int i = 0; i < 4; i++) {
        int r = rowBase + ty * 4 + i;
        if (r >= MTOT) continue;
        int b = r / SEQ, s = r % SEQ;
        float vals[4];
        unpack2(accp[i][0], vals[0], vals[1]);
        unpack2(accp[i][1], vals[2], vals[3]);
#pragma unroll
        for (int j = 0; j < 4; j++) {
            int col = colBase + tx * 4 + j;
            float v = vals[j] + bias[col];
            size_t dst = (s == 0)
                       ? cls_off + (size_t)b * CDIM + col
                       : ((size_t)b * NPIX + (s - 1)) * CDIM + col;
            out[dst] = v;
        }
    }
}

// ---------------------------------------------------------------------------
extern "C" void kernel_launch(void* const* d_in, const int* in_sizes, int n_in,
                              void* d_out, int out_size)
{
    const float* x      = (const float*)d_in[0];
    const float* cls    = (const float*)d_in[1];
    const float* qkv_w  = (const float*)d_in[2];
    const float* proj_w = (const float*)d_in[3];
    const float* proj_b = (const float*)d_in[4];
    const float* lepe_w = (const float*)d_in[5];
    const float* lepe_b = (const float*)d_in[6];
    float* out = (float*)d_out;

    dim3 g1((MTOT + 63) / 64, QKV_N / 64);        // 197 x 12
    qkv_gemm_kernel<<<g1, 256>>>(x, cls, qkv_w);

    dim3 g2((SEQ + 255) / 256, HEADS, BATCH);     // 13 x 8 x 4
    flash_attn_tc_kernel<<<g2, 256>>>();

    lepe_kernel<<<BATCH * HW * 7, 256>>>(x, lepe_w, lepe_b);

    dim3 g4((MTOT + 63) / 64, CDIM / 64);         // 197 x 4
    proj_gemm_kernel<<<g4, 256>>>(proj_w, proj_b, out);
}

// round 13
// speedup vs baseline: 3.3089x; 1.5260x over previous
#include <cuda_runtime.h>
#include <cstdint>

#define BATCH 4
#define HEADS 8
#define SEQ   3137          // 1 cls + 56*56
#define HD    32
#define CDIM  256
#define HW    56
#define NPIX  (HW*HW)       // 3136
#define MTOT  (BATCH*SEQ)   // 12548
#define QKV_N 768

typedef unsigned long long u64;

// ---------------- packed fp32x2 helpers (sm_100+ f32x2 pipe) ---------------
__device__ __forceinline__ u64 packdup(float x) {
    u64 r; asm("mov.b64 %0, {%1, %1};" : "=l"(r) : "f"(x)); return r;
}
__device__ __forceinline__ void fma2(u64 &d, u64 a, u64 b) {
    asm("fma.rn.f32x2 %0, %1, %2, %0;" : "+l"(d) : "l"(a), "l"(b));
}
__device__ __forceinline__ void unpack2(u64 v, float &x, float &y) {
    asm("mov.b64 {%0, %1}, %2;" : "=f"(x), "=f"(y) : "l"(v));
}
__device__ __forceinline__ void lds2(u64 &a, u64 &b, const void *p) {
    unsigned addr = (unsigned)__cvta_generic_to_shared(p);
    asm volatile("ld.shared.v2.u64 {%0, %1}, [%2];" : "=l"(a), "=l"(b) : "r"(addr));
}

// ---------------- bf16 mma helpers ----------------------------------------
// split f0,f1 into packed bf16x2 big (hi=f1,lo=f0) + packed bf16x2 residual
__device__ __forceinline__ void split_bf16(float f0, float f1,
                                           unsigned &big, unsigned &sml) {
    asm("cvt.rn.bf16x2.f32 %0, %1, %2;" : "=r"(big) : "f"(f1), "f"(f0));
    float r0 = f0 - __uint_as_float(big << 16);
    float r1 = f1 - __uint_as_float(big & 0xffff0000u);
    asm("cvt.rn.bf16x2.f32 %0, %1, %2;" : "=r"(sml) : "f"(r1), "f"(r0));
}
__device__ __forceinline__ void mma_bf16(float c[4], const unsigned a[4],
                                         unsigned b0, unsigned b1) {
    asm volatile(
        "mma.sync.aligned.m16n8k16.row.col.f32.bf16.bf16.f32 "
        "{%0,%1,%2,%3}, {%4,%5,%6,%7}, {%8,%9}, {%0,%1,%2,%3};"
        : "+f"(c[0]), "+f"(c[1]), "+f"(c[2]), "+f"(c[3])
        : "r"(a[0]), "r"(a[1]), "r"(a[2]), "r"(a[3]), "r"(b0), "r"(b1));
}

// ---------------- scratch (device globals; no allocation allowed) ----------
__device__ float g_Q[(size_t)BATCH*HEADS*SEQ*HD];
__device__ float g_K[(size_t)BATCH*HEADS*SEQ*HD];
__device__ float g_V[(size_t)BATCH*HEADS*SEQ*HD];
__device__ float g_O[(size_t)BATCH*SEQ*CDIM];

// ---------------------------------------------------------------------------
// Kernel 1: QKV GEMM (M=12548, N=768, K=256), packed f32x2 micro-kernel.
// ---------------------------------------------------------------------------
__global__ __launch_bounds__(256) void qkv_gemm_kernel(
    const float* __restrict__ x, const float* __restrict__ cls,
    const float* __restrict__ w)
{
    __shared__ float Ash[16][64];
    __shared__ float Wsh[16][64];

    const int t  = threadIdx.x;
    const int tx = t & 15;
    const int ty = t >> 4;
    const int rowBase = blockIdx.x * 64;
    const int colBase = blockIdx.y * 64;

    const int lm = t >> 2;
    const int lk = (t & 3) * 4;

    const float* arow = nullptr;
    {
        int gr = rowBase + lm;
        if (gr < MTOT) {
            int b = gr / SEQ, s = gr % SEQ;
            arow = (s == 0) ? (cls + (size_t)b * CDIM)
                            : (x + ((size_t)b * NPIX + (s - 1)) * CDIM);
        }
    }
    const float* wrow = w + (size_t)(colBase + lm) * CDIM;

    u64 accp[4][2] = {};

    for (int k0 = 0; k0 < CDIM; k0 += 16) {
        float4 av = arow ? *(const float4*)(arow + k0 + lk)
                         : make_float4(0.f, 0.f, 0.f, 0.f);
        float4 wv = *(const float4*)(wrow + k0 + lk);
        __syncthreads();
        Ash[lk + 0][lm] = av.x; Ash[lk + 1][lm] = av.y;
        Ash[lk + 2][lm] = av.z; Ash[lk + 3][lm] = av.w;
        Wsh[lk + 0][lm] = wv.x; Wsh[lk + 1][lm] = wv.y;
        Wsh[lk + 2][lm] = wv.z; Wsh[lk + 3][lm] = wv.w;
        __syncthreads();
#pragma unroll
        for (int kk = 0; kk < 16; kk++) {
            float4 a4 = *(const float4*)&Ash[kk][ty * 4];
            u64 w01, w23; lds2(w01, w23, &Wsh[kk][tx * 4]);
            u64 aD;
            aD = packdup(a4.x); fma2(accp[0][0], aD, w01); fma2(accp[0][1], aD, w23);
            aD = packdup(a4.y); fma2(accp[1][0], aD, w01); fma2(accp[1][1], aD, w23);
            aD = packdup(a4.z); fma2(accp[2][0], aD, w01); fma2(accp[2][1], aD, w23);
            aD = packdup(a4.w); fma2(accp[3][0], aD, w01); fma2(accp[3][1], aD, w23);
        }
    }

    const float scale = 0.17677669529663689f;  // 32^-0.5
#pragma unroll
    for (int i = 0; i < 4; i++) {
        int r = rowBase + ty * 4 + i;
        if (r >= MTOT) continue;
        int b = r / SEQ, s = r % SEQ;
        float vals[4];
        unpack2(accp[i][0], vals[0], vals[1]);
        unpack2(accp[i][1], vals[2], vals[3]);
#pragma unroll
        for (int j = 0; j < 4; j++) {
            int col   = colBase + tx * 4 + j;
            int which = col >> 8;
            int f     = col & 255;
            int head  = f >> 5;
            int d     = f & 31;
            size_t dst = (((size_t)(b * HEADS + head)) * SEQ + s) * HD + d;
            float v = vals[j];
            if (which == 0)      g_Q[dst] = v * scale;
            else if (which == 1) g_K[dst] = v;
            else                 g_V[dst] = v;
        }
    }
}

// ---------------------------------------------------------------------------
// Kernel 2: flash attention, bf16 m16n8k16 tensor cores (3-pass compensated),
// m32 per warp, fragment-major packed smem, pipelined staging, shuffle-free
// P re-fragmentation (k16 geometry makes P's A-frag = own C-frag elements).
// Block = 256 thr (8 warps) = 256 queries; 64-key chunks.
// ---------------------------------------------------------------------------
__global__ __launch_bounds__(256, 1) void flash_attn_tc_kernel()
{
    const int b  = blockIdx.z;
    const int h  = blockIdx.y;
    const int qt = blockIdx.x;

    const float* Qg = g_Q + ((size_t)(b * HEADS + h)) * SEQ * HD;
    const float* Kg = g_K + ((size_t)(b * HEADS + h)) * SEQ * HD;
    const float* Vg = g_V + ((size_t)(b * HEADS + h)) * SEQ * HD;

    // fragment-major packed tiles: float4 {b0, b1, s0, s1} (bf16x2 words)
    __shared__ float KP[16 * 32 * 4];   // (nt*2+kc, lane) -> 8 KB
    __shared__ float VP[16 * 32 * 4];   // (kc*4+nt, lane) -> 8 KB

    const int t    = threadIdx.x;
    const int warp = t >> 5;
    const int lane = t & 31;
    const int g    = lane >> 2;
    const int tq   = lane & 3;

    const int qbase = qt * 256 + warp * 32;

    // ---- resident Q fragments, 2 row-halves, bf16 big/small, 2 k16-chunks --
    unsigned qb[2][2][4], qs[2][2][4];
#pragma unroll
    for (int hb = 0; hb < 2; hb++) {
        int r0 = qbase + hb * 16 + g;     if (r0 > SEQ - 1) r0 = SEQ - 1;
        int r1 = qbase + hb * 16 + g + 8; if (r1 > SEQ - 1) r1 = SEQ - 1;
#pragma unroll
        for (int kc = 0; kc < 2; kc++) {
            const float* p0 = Qg + (size_t)r0 * HD + 16 * kc + 2 * tq;
            const float* p1 = Qg + (size_t)r1 * HD + 16 * kc + 2 * tq;
            float2 a = *(const float2*)p0;
            float2 c = *(const float2*)(p0 + 8);
            float2 d = *(const float2*)(p1 + 8);
            float2 e = *(const float2*)p1;
            split_bf16(a.x, a.y, qb[hb][kc][0], qs[hb][kc][0]);
            split_bf16(e.x, e.y, qb[hb][kc][1], qs[hb][kc][1]);
            split_bf16(c.x, c.y, qb[hb][kc][2], qs[hb][kc][2]);
            split_bf16(d.x, d.y, qb[hb][kc][3], qs[hb][kc][3]);
        }
    }

    float O[2][4][4] = {};
    float m_run[2][2] = {{-1e30f, -1e30f}, {-1e30f, -1e30f}};
    float l_run[2][2] = {{0.f, 0.f}, {0.f, 0.f}};

    const int NKT = (SEQ + 63) / 64;    // 50
    const int vkc = warp >> 1;          // staging: this warp's V k-chunk
    const int vnb = (warp & 1) * 2;     // staging: this warp's V nt pair

    // ---- prologue: raw-load chunk 0 into registers ----
    float2 kst2[4];
    float  vst[8];
    {
        int key = warp * 8 + g; if (key > SEQ - 1) key = SEQ - 1;
        const float* kr = Kg + (size_t)key * HD + 2 * tq;
        kst2[0] = *(const float2*)(kr);
        kst2[1] = *(const float2*)(kr + 8);
        kst2[2] = *(const float2*)(kr + 16);
        kst2[3] = *(const float2*)(kr + 24);
        int k0 = 16 * vkc + 2 * tq;
        int ka = k0,     kb2 = k0 + 1, kc2 = k0 + 8, kd = k0 + 9;
        if (ka  > SEQ - 1) ka  = SEQ - 1;
        if (kb2 > SEQ - 1) kb2 = SEQ - 1;
        if (kc2 > SEQ - 1) kc2 = SEQ - 1;
        if (kd  > SEQ - 1) kd  = SEQ - 1;
#pragma unroll
        for (int ln = 0; ln < 2; ln++) {
            int d = (vnb + ln) * 8 + g;
            vst[ln * 4 + 0] = Vg[(size_t)ka  * HD + d];
            vst[ln * 4 + 1] = Vg[(size_t)kb2 * HD + d];
            vst[ln * 4 + 2] = Vg[(size_t)kc2 * HD + d];
            vst[ln * 4 + 3] = Vg[(size_t)kd  * HD + d];
        }
    }

    for (int kt = 0; kt < NKT; kt++) {
        const int kbase = kt * 64;

        __syncthreads();   // prior chunk's smem reads complete
        // ---- decompose + store staged registers (packed bf16 layout) ----
        {
#pragma unroll
            for (int kc = 0; kc < 2; kc++) {
                unsigned b01, s01, b89, s89;
                split_bf16(kst2[2 * kc].x,     kst2[2 * kc].y,     b01, s01);
                split_bf16(kst2[2 * kc + 1].x, kst2[2 * kc + 1].y, b89, s89);
                *(float4*)&KP[(((warp * 2 + kc) * 32) + lane) * 4] =
                    make_float4(__uint_as_float(b01), __uint_as_float(b89),
                                __uint_as_float(s01), __uint_as_float(s89));
            }
#pragma unroll
            for (int ln = 0; ln < 2; ln++) {
                unsigned vb0, vs0, vb1, vs1;
                split_bf16(vst[ln * 4 + 0], vst[ln * 4 + 1], vb0, vs0);
                split_bf16(vst[ln * 4 + 2], vst[ln * 4 + 3], vb1, vs1);
                *(float4*)&VP[(((vkc * 4 + vnb + ln) * 32) + lane) * 4] =
                    make_float4(__uint_as_float(vb0), __uint_as_float(vb1),
                                __uint_as_float(vs0), __uint_as_float(vs1));
            }
        }
        __syncthreads();

        // ---- prefetch raw chunk kt+1 (overlaps with compute below) ----
        if (kt + 1 < NKT) {
            int nb = (kt + 1) * 64;
            int key = nb + warp * 8 + g; if (key > SEQ - 1) key = SEQ - 1;
            const float* kr = Kg + (size_t)key * HD + 2 * tq;
            kst2[0] = *(const float2*)(kr);
            kst2[1] = *(const float2*)(kr + 8);
            kst2[2] = *(const float2*)(kr + 16);
            kst2[3] = *(const float2*)(kr + 24);
            int k0 = nb + 16 * vkc + 2 * tq;
            int ka = k0,     kb2 = k0 + 1, kc2 = k0 + 8, kd = k0 + 9;
            if (ka  > SEQ - 1) ka  = SEQ - 1;
            if (kb2 > SEQ - 1) kb2 = SEQ - 1;
            if (kc2 > SEQ - 1) kc2 = SEQ - 1;
            if (kd  > SEQ - 1) kd  = SEQ - 1;
#pragma unroll
            for (int ln = 0; ln < 2; ln++) {
                int d = (vnb + ln) * 8 + g;
                vst[ln * 4 + 0] = Vg[(size_t)ka  * HD + d];
                vst[ln * 4 + 1] = Vg[(size_t)kb2 * HD + d];
                vst[ln * 4 + 2] = Vg[(size_t)kc2 * HD + d];
                vst[ln * 4 + 3] = Vg[(size_t)kd  * HD + d];
            }
        }

        // ---- S = Q K^T : 8 n-tiles, 2 k16-chunks, 3-pass bf16 ----
        float s[2][8][4];
#pragma unroll
        for (int nt = 0; nt < 8; nt++) {
#pragma unroll
            for (int hb = 0; hb < 2; hb++) {
                s[hb][nt][0] = 0.f; s[hb][nt][1] = 0.f;
                s[hb][nt][2] = 0.f; s[hb][nt][3] = 0.f;
            }
#pragma unroll
            for (int kc = 0; kc < 2; kc++) {
                float4 kf = *(const float4*)&KP[(((nt * 2 + kc) * 32) + lane) * 4];
                unsigned kb0 = __float_as_uint(kf.x), kb1 = __float_as_uint(kf.y);
                unsigned ks0 = __float_as_uint(kf.z), ks1 = __float_as_uint(kf.w);
#pragma unroll
                for (int hb = 0; hb < 2; hb++) {
                    mma_bf16(s[hb][nt], qb[hb][kc], kb0, kb1);
                    mma_bf16(s[hb][nt], qs[hb][kc], kb0, kb1);
                    mma_bf16(s[hb][nt], qb[hb][kc], ks0, ks1);
                }
            }
        }

        // ---- mask invalid keys (only last chunk) ----
        if (kbase + 64 > SEQ) {
#pragma unroll
            for (int nt = 0; nt < 8; nt++) {
                int c = kbase + nt * 8 + 2 * tq;
#pragma unroll
                for (int hb = 0; hb < 2; hb++) {
                    if (c     >= SEQ) { s[hb][nt][0] = -1e30f; s[hb][nt][2] = -1e30f; }
                    if (c + 1 >= SEQ) { s[hb][nt][1] = -1e30f; s[hb][nt][3] = -1e30f; }
                }
            }
        }

        // ---- online softmax per half ----
#pragma unroll
        for (int hb = 0; hb < 2; hb++) {
            float mx0 = -1e30f, mx1 = -1e30f;
#pragma unroll
            for (int nt = 0; nt < 8; nt++) {
                mx0 = fmaxf(mx0, fmaxf(s[hb][nt][0], s[hb][nt][1]));
                mx1 = fmaxf(mx1, fmaxf(s[hb][nt][2], s[hb][nt][3]));
            }
            mx0 = fmaxf(mx0, __shfl_xor_sync(0xffffffffu, mx0, 1));
            mx0 = fmaxf(mx0, __shfl_xor_sync(0xffffffffu, mx0, 2));
            mx1 = fmaxf(mx1, __shfl_xor_sync(0xffffffffu, mx1, 1));
            mx1 = fmaxf(mx1, __shfl_xor_sync(0xffffffffu, mx1, 2));
            float mn0 = fmaxf(m_run[hb][0], mx0);
            float mn1 = fmaxf(m_run[hb][1], mx1);
            float corr0 = __expf(m_run[hb][0] - mn0);
            float corr1 = __expf(m_run[hb][1] - mn1);

            float ls0 = 0.f, ls1 = 0.f;
#pragma unroll
            for (int nt = 0; nt < 8; nt++) {
                s[hb][nt][0] = __expf(s[hb][nt][0] - mn0);
                s[hb][nt][1] = __expf(s[hb][nt][1] - mn0);
                s[hb][nt][2] = __expf(s[hb][nt][2] - mn1);
                s[hb][nt][3] = __expf(s[hb][nt][3] - mn1);
                ls0 += s[hb][nt][0] + s[hb][nt][1];
                ls1 += s[hb][nt][2] + s[hb][nt][3];
            }
            ls0 += __shfl_xor_sync(0xffffffffu, ls0, 1);
            ls0 += __shfl_xor_sync(0xffffffffu, ls0, 2);
            ls1 += __shfl_xor_sync(0xffffffffu, ls1, 1);
            ls1 += __shfl_xor_sync(0xffffffffu, ls1, 2);
            l_run[hb][0] = l_run[hb][0] * corr0 + ls0;  m_run[hb][0] = mn0;
            l_run[hb][1] = l_run[hb][1] * corr1 + ls1;  m_run[hb][1] = mn1;

#pragma unroll
            for (int nt = 0; nt < 4; nt++) {
                O[hb][nt][0] *= corr0; O[hb][nt][1] *= corr0;
                O[hb][nt][2] *= corr1; O[hb][nt][3] *= corr1;
            }
        }

        // ---- O += P V : shuffle-free P frag (own C-frag elements), bf16 ----
#pragma unroll
        for (int kc = 0; kc < 4; kc++) {
            unsigned pb[2][4], ps[2][4];
#pragma unroll
            for (int hb = 0; hb < 2; hb++) {
                split_bf16(s[hb][2*kc][0],   s[hb][2*kc][1],   pb[hb][0], ps[hb][0]);
                split_bf16(s[hb][2*kc][2],   s[hb][2*kc][3],   pb[hb][1], ps[hb][1]);
                split_bf16(s[hb][2*kc+1][0], s[hb][2*kc+1][1], pb[hb][2], ps[hb][2]);
                split_bf16(s[hb][2*kc+1][2], s[hb][2*kc+1][3], pb[hb][3], ps[hb][3]);
            }
#pragma unroll
            for (int nt = 0; nt < 4; nt++) {
                float4 vf = *(const float4*)&VP[(((kc * 4 + nt) * 32) + lane) * 4];
                unsigned vb0 = __float_as_uint(vf.x), vb1 = __float_as_uint(vf.y);
                unsigned vs0 = __float_as_uint(vf.z), vs1 = __float_as_uint(vf.w);
#pragma unroll
                for (int hb = 0; hb < 2; hb++) {
                    mma_bf16(O[hb][nt], pb[hb], vb0, vb1);
                    mma_bf16(O[hb][nt], ps[hb], vb0, vb1);
                    mma_bf16(O[hb][nt], pb[hb], vs0, vs1);
                }
            }
        }
    }

    // ---- epilogue ----
#pragma unroll
    for (int hb = 0; hb < 2; hb++) {
        float inv0 = 1.f / l_run[hb][0], inv1 = 1.f / l_run[hb][1];
        int r0 = qbase + hb * 16 + g;
        int r1 = qbase + hb * 16 + g + 8;
#pragma unroll
        for (int nt = 0; nt < 4; nt++) {
            int col = h * HD + nt * 8 + 2 * tq;
            if (r0 < SEQ) {
                float2 v = make_float2(O[hb][nt][0] * inv0, O[hb][nt][1] * inv0);
                *(float2*)&g_O[((size_t)b * SEQ + r0) * CDIM + col] = v;
            }
            if (r1 < SEQ) {
                float2 v = make_float2(O[hb][nt][2] * inv1, O[hb][nt][3] * inv1);
                *(float2*)&g_O[((size_t)b * SEQ + r1) * CDIM + col] = v;
            }
        }
    }
}

// ---------------------------------------------------------------------------
// Kernel 3: depthwise 5x5 LePE (NHWC, SAME), adds into g_O rows 1..3136.
// ---------------------------------------------------------------------------
__global__ __launch_bounds__(256) void lepe_kernel(
    const float* __restrict__ x, const float* __restrict__ w,
    const float* __restrict__ bias)
{
    __shared__ float ws[CDIM * 25];
    const int c = threadIdx.x;
    for (int idx = c; idx < CDIM * 25; idx += 256) ws[idx] = w[idx];
    __syncthreads();

    const int blk  = blockIdx.x;         // 0 .. 4*56*7-1
    const int b    = blk / (HW * 7);
    const int rem  = blk % (HW * 7);
    const int hh   = rem / 7;
    const int ww0  = (rem % 7) * 8;
    const float bc = bias[c];

#pragma unroll
    for (int p = 0; p < 8; p++) {
        int ww = ww0 + p;
        float sum = bc;
#pragma unroll
        for (int dy = 0; dy < 5; dy++) {
            int y = hh + dy - 2;
            if (y < 0 || y >= HW) continue;
#pragma unroll
            for (int dx = 0; dx < 5; dx++) {
                int xx = ww + dx - 2;
                if (xx < 0 || xx >= HW) continue;
                sum = fmaf(x[(((size_t)b * HW + y) * HW + xx) * CDIM + c],
                           ws[c * 25 + dy * 5 + dx], sum);
            }
        }
        int hw = hh * HW + ww;
        g_O[((size_t)b * SEQ + 1 + hw) * CDIM + c] += sum;
    }
}

// ---------------------------------------------------------------------------
// Kernel 4: proj GEMM (12548 x 256 x 256), packed f32x2, +bias, split output.
// ---------------------------------------------------------------------------
__global__ __launch_bounds__(256) void proj_gemm_kernel(
    const float* __restrict__ w, const float* __restrict__ bias,
    float* __restrict__ out)
{
    __shared__ float Ash[16][64];
    __shared__ float Wsh[16][64];

    const int t  = threadIdx.x;
    const int tx = t & 15;
    const int ty = t >> 4;
    const int rowBase = blockIdx.x * 64;
    const int colBase = blockIdx.y * 64;

    const int lm = t >> 2;
    const int lk = (t & 3) * 4;

    const float* arow = (rowBase + lm < MTOT)
                      ? (g_O + (size_t)(rowBase + lm) * CDIM) : nullptr;
    const float* wrow = w + (size_t)(colBase + lm) * CDIM;

    u64 accp[4][2] = {};

    for (int k0 = 0; k0 < CDIM; k0 += 16) {
        float4 av = arow ? *(const float4*)(arow + k0 + lk)
                         : make_float4(0.f, 0.f, 0.f, 0.f);
        float4 wv = *(const float4*)(wrow + k0 + lk);
        __syncthreads();
        Ash[lk + 0][lm] = av.x; Ash[lk + 1][lm] = av.y;
        Ash[lk + 2][lm] = av.z; Ash[lk + 3][lm] = av.w;
        Wsh[lk + 0][lm] = wv.x; Wsh[lk + 1][lm] = wv.y;
        Wsh[lk + 2][lm] = wv.z; Wsh[lk + 3][lm] = wv.w;
        __syncthreads();
#pragma unroll
        for (int kk = 0; kk < 16; kk++) {
            float4 a4 = *(const float4*)&Ash[kk][ty * 4];
            u64 w01, w23; lds2(w01, w23, &Wsh[kk][tx * 4]);
            u64 aD;
            aD = packdup(a4.x); fma2(accp[0][0], aD, w01); fma2(accp[0][1], aD, w23);
            aD = packdup(a4.y); fma2(accp[1][0], aD, w01); fma2(accp[1][1], aD, w23);
            aD = packdup(a4.z); fma2(accp[2][0], aD, w01); fma2(accp[2][1], aD, w23);
            aD = packdup(a4.w); fma2(accp[3][0], aD, w01); fma2(accp[3][1], aD, w23);
        }
    }

    const size_t cls_off = (size_t)BATCH * NPIX * CDIM;
#pragma unroll
    for (int i = 0; i < 4; i++) {
        int r = rowBase + ty * 4 + i;
        if (r >= MTOT) continue;
        int b = r / SEQ, s = r % SEQ;
        float vals[4];
        unpack2(accp[i][0], vals[0], vals[1]);
        unpack2(accp[i][1], vals[2], vals[3]);
#pragma unroll
        for (int j = 0; j < 4; j++) {
            int col = colBase + tx * 4 + j;
            float v = vals[j] + bias[col];
            size_t dst = (s == 0)
                       ? cls_off + (size_t)b * CDIM + col
                       : ((size_t)b * NPIX + (s - 1)) * CDIM + col;
            out[dst] = v;
        }
    }
}

// ---------------------------------------------------------------------------
extern "C" void kernel_launch(void* const* d_in, const int* in_sizes, int n_in,
                              void* d_out, int out_size)
{
    const float* x      = (const float*)d_in[0];
    const float* cls    = (const float*)d_in[1];
    const float* qkv_w  = (const float*)d_in[2];
    const float* proj_w = (const float*)d_in[3];
    const float* proj_b = (const float*)d_in[4];
    const float* lepe_w = (const float*)d_in[5];
    const float* lepe_b = (const float*)d_in[6];
    float* out = (float*)d_out;

    dim3 g1((MTOT + 63) / 64, QKV_N / 64);        // 197 x 12
    qkv_gemm_kernel<<<g1, 256>>>(x, cls, qkv_w);

    dim3 g2((SEQ + 255) / 256, HEADS, BATCH);     // 13 x 8 x 4
    flash_attn_tc_kernel<<<g2, 256>>>();

    lepe_kernel<<<BATCH * HW * 7, 256>>>(x, lepe_w, lepe_b);

    dim3 g4((MTOT + 63) / 64, CDIM / 64);         // 197 x 4
    proj_gemm_kernel<<<g4, 256>>>(proj_w, proj_b, out);
}

// round 15
// speedup vs baseline: 4.1522x; 1.2549x over previous
#include <cuda_runtime.h>
#include <cstdint>

#define BATCH 4
#define HEADS 8
#define SEQ   3137          // 1 cls + 56*56
#define HD    32
#define CDIM  256
#define HW    56
#define NPIX  (HW*HW)       // 3136
#define MTOT  (BATCH*SEQ)   // 12548
#define QKV_N 768

// ---------------- bf16 mma helpers ----------------------------------------
// split f0,f1 into packed bf16x2 big (hi=f1,lo=f0) + packed bf16x2 residual
__device__ __forceinline__ void split_bf16(float f0, float f1,
                                           unsigned &big, unsigned &sml) {
    asm("cvt.rn.bf16x2.f32 %0, %1, %2;" : "=r"(big) : "f"(f1), "f"(f0));
    float r0 = f0 - __uint_as_float(big << 16);
    float r1 = f1 - __uint_as_float(big & 0xffff0000u);
    asm("cvt.rn.bf16x2.f32 %0, %1, %2;" : "=r"(sml) : "f"(r1), "f"(r0));
}
__device__ __forceinline__ void mma_bf16(float c[4], const unsigned a[4],
                                         unsigned b0, unsigned b1) {
    asm volatile(
        "mma.sync.aligned.m16n8k16.row.col.f32.bf16.bf16.f32 "
        "{%0,%1,%2,%3}, {%4,%5,%6,%7}, {%8,%9}, {%0,%1,%2,%3};"
        : "+f"(c[0]), "+f"(c[1]), "+f"(c[2]), "+f"(c[3])
        : "r"(a[0]), "r"(a[1]), "r"(a[2]), "r"(a[3]), "r"(b0), "r"(b1));
}

// ---------------- scratch (device globals; no allocation allowed) ----------
__device__ float g_Q[(size_t)BATCH*HEADS*SEQ*HD];
__device__ float g_K[(size_t)BATCH*HEADS*SEQ*HD];
__device__ float g_V[(size_t)BATCH*HEADS*SEQ*HD];
__device__ float g_O[(size_t)BATCH*SEQ*CDIM];

// ---------------------------------------------------------------------------
// Kernel 1: QKV GEMM on tensor cores (bf16 3-pass). M=12548, N=768, K=256.
// Block 128 thr (4 warps), tile 64 rows x 128 cols. W fragments staged in
// smem (shared by all warps); A fragments straight from gmem, double-buffered.
// ---------------------------------------------------------------------------
__global__ __launch_bounds__(128) void qkv_gemm_tc_kernel(
    const float* __restrict__ x, const float* __restrict__ cls,
    const float* __restrict__ w)
{
    __shared__ float WP[16 * 32 * 4];   // 16 n-tile fragment slots, 8 KB

    const int t    = threadIdx.x;
    const int warp = t >> 5;
    const int lane = t & 31;
    const int g    = lane >> 2;
    const int tq   = lane & 3;

    const int rowBase = blockIdx.x * 64;
    const int colBase = blockIdx.y * 128;

    const int r0 = rowBase + warp * 16 + g;
    const int r1 = r0 + 8;
    int r0c = r0 < MTOT ? r0 : MTOT - 1;
    int r1c = r1 < MTOT ? r1 : MTOT - 1;

    const float* arow0;
    const float* arow1;
    {
        int b0 = r0c / SEQ, s0 = r0c % SEQ;
        arow0 = (s0 == 0) ? (cls + (size_t)b0 * CDIM)
                          : (x + ((size_t)b0 * NPIX + (s0 - 1)) * CDIM);
        int b1 = r1c / SEQ, s1 = r1c % SEQ;
        arow1 = (s1 == 0) ? (cls + (size_t)b1 * CDIM)
                          : (x + ((size_t)b1 * NPIX + (s1 - 1)) * CDIM);
    }

    float acc[16][4];
#pragma unroll
    for (int nt = 0; nt < 16; nt++) {
        acc[nt][0] = 0.f; acc[nt][1] = 0.f; acc[nt][2] = 0.f; acc[nt][3] = 0.f;
    }

    float2 ast[2][4];
    float2 wst[2][8];

    // prologue: iter 0 raw loads
    {
        ast[0][0] = *(const float2*)(arow0 + 2 * tq);
        ast[0][1] = *(const float2*)(arow1 + 2 * tq);
        ast[0][2] = *(const float2*)(arow0 + 2 * tq + 8);
        ast[0][3] = *(const float2*)(arow1 + 2 * tq + 8);
#pragma unroll
        for (int ln = 0; ln < 4; ln++) {
            const float* wr = w + (size_t)(colBase + (warp * 4 + ln) * 8 + g) * CDIM + 2 * tq;
            wst[0][2 * ln]     = *(const float2*)wr;
            wst[0][2 * ln + 1] = *(const float2*)(wr + 8);
        }
    }

#pragma unroll
    for (int iter = 0; iter < 16; iter++) {
        const int cur = iter & 1, nxt = cur ^ 1;
        __syncthreads();
#pragma unroll
        for (int ln = 0; ln < 4; ln++) {
            unsigned b01, s01, b89, s89;
            split_bf16(wst[cur][2 * ln].x,     wst[cur][2 * ln].y,     b01, s01);
            split_bf16(wst[cur][2 * ln + 1].x, wst[cur][2 * ln + 1].y, b89, s89);
            *(float4*)&WP[(((warp * 4 + ln) * 32) + lane) * 4] =
                make_float4(__uint_as_float(b01), __uint_as_float(b89),
                            __uint_as_float(s01), __uint_as_float(s89));
        }
        __syncthreads();

        if (iter < 15) {
            int k0 = 16 * (iter + 1);
            ast[nxt][0] = *(const float2*)(arow0 + k0 + 2 * tq);
            ast[nxt][1] = *(const float2*)(arow1 + k0 + 2 * tq);
            ast[nxt][2] = *(const float2*)(arow0 + k0 + 2 * tq + 8);
            ast[nxt][3] = *(const float2*)(arow1 + k0 + 2 * tq + 8);
#pragma unroll
            for (int ln = 0; ln < 4; ln++) {
                const float* wr = w + (size_t)(colBase + (warp * 4 + ln) * 8 + g) * CDIM + k0 + 2 * tq;
                wst[nxt][2 * ln]     = *(const float2*)wr;
                wst[nxt][2 * ln + 1] = *(const float2*)(wr + 8);
            }
        }

        unsigned ab[4], as[4];
        split_bf16(ast[cur][0].x, ast[cur][0].y, ab[0], as[0]);
        split_bf16(ast[cur][1].x, ast[cur][1].y, ab[1], as[1]);
        split_bf16(ast[cur][2].x, ast[cur][2].y, ab[2], as[2]);
        split_bf16(ast[cur][3].x, ast[cur][3].y, ab[3], as[3]);

#pragma unroll
        for (int nt = 0; nt < 16; nt++) {
            float4 wf = *(const float4*)&WP[((nt * 32) + lane) * 4];
            unsigned wb0 = __float_as_uint(wf.x), wb1 = __float_as_uint(wf.y);
            unsigned ws0 = __float_as_uint(wf.z), ws1 = __float_as_uint(wf.w);
            mma_bf16(acc[nt], ab, wb0, wb1);
            mma_bf16(acc[nt], as, wb0, wb1);
            mma_bf16(acc[nt], ab, ws0, ws1);
        }
    }

    // epilogue: scatter into g_Q (scaled) / g_K / g_V
    const float scale = 0.17677669529663689f;  // 32^-0.5
#pragma unroll
    for (int half = 0; half < 2; half++) {
        int r = half ? r1 : r0;
        if (r >= MTOT) continue;
        int b = r / SEQ, s = r % SEQ;
#pragma unroll
        for (int nt = 0; nt < 16; nt++) {
            int col   = colBase + nt * 8 + 2 * tq;
            int which = col >> 8;
            int f     = col & 255;
            int head  = f >> 5;
            int d     = f & 31;
            size_t dst = (((size_t)(b * HEADS + head)) * SEQ + s) * HD + d;
            float v0 = acc[nt][half * 2 + 0];
            float v1 = acc[nt][half * 2 + 1];
            if (which == 0) {
                *(float2*)&g_Q[dst] = make_float2(v0 * scale, v1 * scale);
            } else if (which == 1) {
                *(float2*)&g_K[dst] = make_float2(v0, v1);
            } else {
                *(float2*)&g_V[dst] = make_float2(v0, v1);
            }
        }
    }
}

// ---------------------------------------------------------------------------
// Kernel 2: flash attention, bf16 m16n8k16 (3-pass), m32 per warp,
// 128-thread blocks (2 blocks/SM for latency hiding), fragment-major smem,
// pipelined staging, shuffle-free P re-fragmentation.
// ---------------------------------------------------------------------------
__global__ __launch_bounds__(128, 2) void flash_attn_tc_kernel()
{
    const int b  = blockIdx.z;
    const int h  = blockIdx.y;
    const int qt = blockIdx.x;

    const float* Qg = g_Q + ((size_t)(b * HEADS + h)) * SEQ * HD;
    const float* Kg = g_K + ((size_t)(b * HEADS + h)) * SEQ * HD;
    const float* Vg = g_V + ((size_t)(b * HEADS + h)) * SEQ * HD;

    __shared__ float KP[16 * 32 * 4];   // (nt*2+kc, lane) -> 8 KB
    __shared__ float VP[16 * 32 * 4];   // (kc*4+nt, lane) -> 8 KB

    const int t    = threadIdx.x;
    const int warp = t >> 5;
    const int lane = t & 31;
    const int g    = lane >> 2;
    const int tq   = lane & 3;

    const int qbase = qt * 128 + warp * 32;

    // ---- resident Q fragments, 2 row-halves, bf16 big/small, 2 k16-chunks --
    unsigned qb[2][2][4], qs[2][2][4];
#pragma unroll
    for (int hb = 0; hb < 2; hb++) {
        int r0 = qbase + hb * 16 + g;     if (r0 > SEQ - 1) r0 = SEQ - 1;
        int r1 = qbase + hb * 16 + g + 8; if (r1 > SEQ - 1) r1 = SEQ - 1;
#pragma unroll
        for (int kc = 0; kc < 2; kc++) {
            const float* p0 = Qg + (size_t)r0 * HD + 16 * kc + 2 * tq;
            const float* p1 = Qg + (size_t)r1 * HD + 16 * kc + 2 * tq;
            float2 a = *(const float2*)p0;
            float2 c = *(const float2*)(p0 + 8);
            float2 d = *(const float2*)(p1 + 8);
            float2 e = *(const float2*)p1;
            split_bf16(a.x, a.y, qb[hb][kc][0], qs[hb][kc][0]);
            split_bf16(e.x, e.y, qb[hb][kc][1], qs[hb][kc][1]);
            split_bf16(c.x, c.y, qb[hb][kc][2], qs[hb][kc][2]);
            split_bf16(d.x, d.y, qb[hb][kc][3], qs[hb][kc][3]);
        }
    }

    float O[2][4][4] = {};
    float m_run[2][2] = {{-1e30f, -1e30f}, {-1e30f, -1e30f}};
    float l_run[2][2] = {{0.f, 0.f}, {0.f, 0.f}};

    const int NKT = (SEQ + 63) / 64;    // 50

    // staging layout (4 warps):
    //  K: warp stages nt = warp*2 + ln (ln 0..1): key row = nt*8 + g
    //  V: warp stages kc = warp, nt = ln (0..3): keys 16*warp + 2tq {+0,+1,+8,+9}, d = ln*8+g
    float2 kst2[2][4];
    float  vst[4][4];

    // ---- prologue: raw-load chunk 0 into registers ----
    {
#pragma unroll
        for (int ln = 0; ln < 2; ln++) {
            int key = warp * 16 + ln * 8 + g; if (key > SEQ - 1) key = SEQ - 1;
            const float* kr = Kg + (size_t)key * HD + 2 * tq;
            kst2[ln][0] = *(const float2*)(kr);
            kst2[ln][1] = *(const float2*)(kr + 8);
            kst2[ln][2] = *(const float2*)(kr + 16);
            kst2[ln][3] = *(const float2*)(kr + 24);
        }
        int k0 = 16 * warp + 2 * tq;
        int ka = k0, kb2 = k0 + 1, kc2 = k0 + 8, kd = k0 + 9;
        if (ka  > SEQ - 1) ka  = SEQ - 1;
        if (kb2 > SEQ - 1) kb2 = SEQ - 1;
        if (kc2 > SEQ - 1) kc2 = SEQ - 1;
        if (kd  > SEQ - 1) kd  = SEQ - 1;
#pragma unroll
        for (int ln = 0; ln < 4; ln++) {
            int d = ln * 8 + g;
            vst[ln][0] = Vg[(size_t)ka  * HD + d];
            vst[ln][1] = Vg[(size_t)kb2 * HD + d];
            vst[ln][2] = Vg[(size_t)kc2 * HD + d];
            vst[ln][3] = Vg[(size_t)kd  * HD + d];
        }
    }

    for (int kt = 0; kt < NKT; kt++) {
        const int kbase = kt * 64;

        __syncthreads();   // prior chunk's smem reads complete
        // ---- decompose + store staged registers (packed bf16 layout) ----
        {
#pragma unroll
            for (int ln = 0; ln < 2; ln++) {
#pragma unroll
                for (int kc = 0; kc < 2; kc++) {
                    unsigned b01, s01, b89, s89;
                    split_bf16(kst2[ln][2 * kc].x,     kst2[ln][2 * kc].y,     b01, s01);
                    split_bf16(kst2[ln][2 * kc + 1].x, kst2[ln][2 * kc + 1].y, b89, s89);
                    *(float4*)&KP[((((warp * 2 + ln) * 2 + kc) * 32) + lane) * 4] =
                        make_float4(__uint_as_float(b01), __uint_as_float(b89),
                                    __uint_as_float(s01), __uint_as_float(s89));
                }
            }
#pragma unroll
            for (int ln = 0; ln < 4; ln++) {
                unsigned vb0, vs0, vb1, vs1;
                split_bf16(vst[ln][0], vst[ln][1], vb0, vs0);
                split_bf16(vst[ln][2], vst[ln][3], vb1, vs1);
                *(float4*)&VP[(((warp * 4 + ln) * 32) + lane) * 4] =
                    make_float4(__uint_as_float(vb0), __uint_as_float(vb1),
                                __uint_as_float(vs0), __uint_as_float(vs1));
            }
        }
        __syncthreads();

        // ---- prefetch raw chunk kt+1 (overlaps with compute below) ----
        if (kt + 1 < NKT) {
            int nb = (kt + 1) * 64;
#pragma unroll
            for (int ln = 0; ln < 2; ln++) {
                int key = nb + warp * 16 + ln * 8 + g; if (key > SEQ - 1) key = SEQ - 1;
                const float* kr = Kg + (size_t)key * HD + 2 * tq;
                kst2[ln][0] = *(const float2*)(kr);
                kst2[ln][1] = *(const float2*)(kr + 8);
                kst2[ln][2] = *(const float2*)(kr + 16);
                kst2[ln][3] = *(const float2*)(kr + 24);
            }
            int k0 = nb + 16 * warp + 2 * tq;
            int ka = k0, kb2 = k0 + 1, kc2 = k0 + 8, kd = k0 + 9;
            if (ka  > SEQ - 1) ka  = SEQ - 1;
            if (kb2 > SEQ - 1) kb2 = SEQ - 1;
            if (kc2 > SEQ - 1) kc2 = SEQ - 1;
            if (kd  > SEQ - 1) kd  = SEQ - 1;
#pragma unroll
            for (int ln = 0; ln < 4; ln++) {
                int d = ln * 8 + g;
                vst[ln][0] = Vg[(size_t)ka  * HD + d];
                vst[ln][1] = Vg[(size_t)kb2 * HD + d];
                vst[ln][2] = Vg[(size_t)kc2 * HD + d];
                vst[ln][3] = Vg[(size_t)kd  * HD + d];
            }
        }

        // ---- S = Q K^T : 8 n-tiles, 2 k16-chunks, 3-pass bf16 ----
        float s[2][8][4];
#pragma unroll
        for (int nt = 0; nt < 8; nt++) {
#pragma unroll
            for (int hb = 0; hb < 2; hb++) {
                s[hb][nt][0] = 0.f; s[hb][nt][1] = 0.f;
                s[hb][nt][2] = 0.f; s[hb][nt][3] = 0.f;
            }
#pragma unroll
            for (int kc = 0; kc < 2; kc++) {
                float4 kf = *(const float4*)&KP[(((nt * 2 + kc) * 32) + lane) * 4];
                unsigned kb0 = __float_as_uint(kf.x), kb1 = __float_as_uint(kf.y);
                unsigned ks0 = __float_as_uint(kf.z), ks1 = __float_as_uint(kf.w);
#pragma unroll
                for (int hb = 0; hb < 2; hb++) {
                    mma_bf16(s[hb][nt], qb[hb][kc], kb0, kb1);
                    mma_bf16(s[hb][nt], qs[hb][kc], kb0, kb1);
                    mma_bf16(s[hb][nt], qb[hb][kc], ks0, ks1);
                }
            }
        }

        // ---- mask invalid keys (only last chunk) ----
        if (kbase + 64 > SEQ) {
#pragma unroll
            for (int nt = 0; nt < 8; nt++) {
                int c = kbase + nt * 8 + 2 * tq;
#pragma unroll
                for (int hb = 0; hb < 2; hb++) {
                    if (c     >= SEQ) { s[hb][nt][0] = -1e30f; s[hb][nt][2] = -1e30f; }
                    if (c + 1 >= SEQ) { s[hb][nt][1] = -1e30f; s[hb][nt][3] = -1e30f; }
                }
            }
        }

        // ---- online softmax per half ----
#pragma unroll
        for (int hb = 0; hb < 2; hb++) {
            float mx0 = -1e30f, mx1 = -1e30f;
#pragma unroll
            for (int nt = 0; nt < 8; nt++) {
                mx0 = fmaxf(mx0, fmaxf(s[hb][nt][0], s[hb][nt][1]));
                mx1 = fmaxf(mx1, fmaxf(s[hb][nt][2], s[hb][nt][3]));
            }
            mx0 = fmaxf(mx0, __shfl_xor_sync(0xffffffffu, mx0, 1));
            mx0 = fmaxf(mx0, __shfl_xor_sync(0xffffffffu, mx0, 2));
            mx1 = fmaxf(mx1, __shfl_xor_sync(0xffffffffu, mx1, 1));
            mx1 = fmaxf(mx1, __shfl_xor_sync(0xffffffffu, mx1, 2));
            float mn0 = fmaxf(m_run[hb][0], mx0);
            float mn1 = fmaxf(m_run[hb][1], mx1);
            float corr0 = __expf(m_run[hb][0] - mn0);
            float corr1 = __expf(m_run[hb][1] - mn1);

            float ls0 = 0.f, ls1 = 0.f;
#pragma unroll
            for (int nt = 0; nt < 8; nt++) {
                s[hb][nt][0] = __expf(s[hb][nt][0] - mn0);
                s[hb][nt][1] = __expf(s[hb][nt][1] - mn0);
                s[hb][nt][2] = __expf(s[hb][nt][2] - mn1);
                s[hb][nt][3] = __expf(s[hb][nt][3] - mn1);
                ls0 += s[hb][nt][0] + s[hb][nt][1];
                ls1 += s[hb][nt][2] + s[hb][nt][3];
            }
            ls0 += __shfl_xor_sync(0xffffffffu, ls0, 1);
            ls0 += __shfl_xor_sync(0xffffffffu, ls0, 2);
            ls1 += __shfl_xor_sync(0xffffffffu, ls1, 1);
            ls1 += __shfl_xor_sync(0xffffffffu, ls1, 2);
            l_run[hb][0] = l_run[hb][0] * corr0 + ls0;  m_run[hb][0] = mn0;
            l_run[hb][1] = l_run[hb][1] * corr1 + ls1;  m_run[hb][1] = mn1;

#pragma unroll
            for (int nt = 0; nt < 4; nt++) {
                O[hb][nt][0] *= corr0; O[hb][nt][1] *= corr0;
                O[hb][nt][2] *= corr1; O[hb][nt][3] *= corr1;
            }
        }

        // ---- O += P V : shuffle-free P frag (own C-frag elements), bf16 ----
#pragma unroll
        for (int kc = 0; kc < 4; kc++) {
            unsigned pb[2][4], ps[2][4];
#pragma unroll
            for (int hb = 0; hb < 2; hb++) {
                split_bf16(s[hb][2*kc][0],   s[hb][2*kc][1],   pb[hb][0], ps[hb][0]);
                split_bf16(s[hb][2*kc][2],   s[hb][2*kc][3],   pb[hb][1], ps[hb][1]);
                split_bf16(s[hb][2*kc+1][0], s[hb][2*kc+1][1], pb[hb][2], ps[hb][2]);
                split_bf16(s[hb][2*kc+1][2], s[hb][2*kc+1][3], pb[hb][3], ps[hb][3]);
            }
#pragma unroll
            for (int nt = 0; nt < 4; nt++) {
                float4 vf = *(const float4*)&VP[(((kc * 4 + nt) * 32) + lane) * 4];
                unsigned vb0 = __float_as_uint(vf.x), vb1 = __float_as_uint(vf.y);
                unsigned vs0 = __float_as_uint(vf.z), vs1 = __float_as_uint(vf.w);
#pragma unroll
                for (int hb = 0; hb < 2; hb++) {
                    mma_bf16(O[hb][nt], pb[hb], vb0, vb1);
                    mma_bf16(O[hb][nt], ps[hb], vb0, vb1);
                    mma_bf16(O[hb][nt], pb[hb], vs0, vs1);
                }
            }
        }
    }

    // ---- epilogue ----
#pragma unroll
    for (int hb = 0; hb < 2; hb++) {
        float inv0 = 1.f / l_run[hb][0], inv1 = 1.f / l_run[hb][1];
        int r0 = qbase + hb * 16 + g;
        int r1 = qbase + hb * 16 + g + 8;
#pragma unroll
        for (int nt = 0; nt < 4; nt++) {
            int col = h * HD + nt * 8 + 2 * tq;
            if (r0 < SEQ) {
                float2 v = make_float2(O[hb][nt][0] * inv0, O[hb][nt][1] * inv0);
                *(float2*)&g_O[((size_t)b * SEQ + r0) * CDIM + col] = v;
            }
            if (r1 < SEQ) {
                float2 v = make_float2(O[hb][nt][2] * inv1, O[hb][nt][3] * inv1);
                *(float2*)&g_O[((size_t)b * SEQ + r1) * CDIM + col] = v;
            }
        }
    }
}

// ---------------------------------------------------------------------------
// Kernel 3: depthwise 5x5 LePE (NHWC, SAME), adds into g_O rows 1..3136.
// ---------------------------------------------------------------------------
__global__ __launch_bounds__(256) void lepe_kernel(
    const float* __restrict__ x, const float* __restrict__ w,
    const float* __restrict__ bias)
{
    __shared__ float ws[CDIM * 25];
    const int c = threadIdx.x;
    for (int idx = c; idx < CDIM * 25; idx += 256) ws[idx] = w[idx];
    __syncthreads();

    const int blk  = blockIdx.x;         // 0 .. 4*56*7-1
    const int b    = blk / (HW * 7);
    const int rem  = blk % (HW * 7);
    const int hh   = rem / 7;
    const int ww0  = (rem % 7) * 8;
    const float bc = bias[c];

#pragma unroll
    for (int p = 0; p < 8; p++) {
        int ww = ww0 + p;
        float sum = bc;
#pragma unroll
        for (int dy = 0; dy < 5; dy++) {
            int y = hh + dy - 2;
            if (y < 0 || y >= HW) continue;
#pragma unroll
            for (int dx = 0; dx < 5; dx++) {
                int xx = ww + dx - 2;
                if (xx < 0 || xx >= HW) continue;
                sum = fmaf(x[(((size_t)b * HW + y) * HW + xx) * CDIM + c],
                           ws[c * 25 + dy * 5 + dx], sum);
            }
        }
        int hw = hh * HW + ww;
        g_O[((size_t)b * SEQ + 1 + hw) * CDIM + c] += sum;
    }
}

// ---------------------------------------------------------------------------
// Kernel 4: proj GEMM on tensor cores (bf16 3-pass). M=12548, N=256, K=256.
// Same template as kernel 1; A rows from g_O; bias + cls/x output split.
// ---------------------------------------------------------------------------
__global__ __launch_bounds__(128) void proj_gemm_tc_kernel(
    const float* __restrict__ w, const float* __restrict__ bias,
    float* __restrict__ out)
{
    __shared__ float WP[16 * 32 * 4];   // 8 KB

    const int t    = threadIdx.x;
    const int warp = t >> 5;
    const int lane = t & 31;
    const int g    = lane >> 2;
    const int tq   = lane & 3;

    const int rowBase = blockIdx.x * 64;
    const int colBase = blockIdx.y * 128;

    const int r0 = rowBase + warp * 16 + g;
    const int r1 = r0 + 8;
    int r0c = r0 < MTOT ? r0 : MTOT - 1;
    int r1c = r1 < MTOT ? r1 : MTOT - 1;
    const float* arow0 = g_O + (size_t)r0c * CDIM;
    const float* arow1 = g_O + (size_t)r1c * CDIM;

    float acc[16][4];
#pragma unroll
    for (int nt = 0; nt < 16; nt++) {
        acc[nt][0] = 0.f; acc[nt][1] = 0.f; acc[nt][2] = 0.f; acc[nt][3] = 0.f;
    }

    float2 ast[2][4];
    float2 wst[2][8];
    {
        ast[0][0] = *(const float2*)(arow0 + 2 * tq);
        ast[0][1] = *(const float2*)(arow1 + 2 * tq);
        ast[0][2] = *(const float2*)(arow0 + 2 * tq + 8);
        ast[0][3] = *(const float2*)(arow1 + 2 * tq + 8);
#pragma unroll
        for (int ln = 0; ln < 4; ln++) {
            const float* wr = w + (size_t)(colBase + (warp * 4 + ln) * 8 + g) * CDIM + 2 * tq;
            wst[0][2 * ln]     = *(const float2*)wr;
            wst[0][2 * ln + 1] = *(const float2*)(wr + 8);
        }
    }

#pragma unroll
    for (int iter = 0; iter < 16; iter++) {
        const int cur = iter & 1, nxt = cur ^ 1;
        __syncthreads();
#pragma unroll
        for (int ln = 0; ln < 4; ln++) {
            unsigned b01, s01, b89, s89;
            split_bf16(wst[cur][2 * ln].x,     wst[cur][2 * ln].y,     b01, s01);
            split_bf16(wst[cur][2 * ln + 1].x, wst[cur][2 * ln + 1].y, b89, s89);
            *(float4*)&WP[(((warp * 4 + ln) * 32) + lane) * 4] =
                make_float4(__uint_as_float(b01), __uint_as_float(b89),
                            __uint_as_float(s01), __uint_as_float(s89));
        }
        __syncthreads();

        if (iter < 15) {
            int k0 = 16 * (iter + 1);
            ast[nxt][0] = *(const float2*)(arow0 + k0 + 2 * tq);
            ast[nxt][1] = *(const float2*)(arow1 + k0 + 2 * tq);
            ast[nxt][2] = *(const float2*)(arow0 + k0 + 2 * tq + 8);
            ast[nxt][3] = *(const float2*)(arow1 + k0 + 2 * tq + 8);
#pragma unroll
            for (int ln = 0; ln < 4; ln++) {
                const float* wr = w + (size_t)(colBase + (warp * 4 + ln) * 8 + g) * CDIM + k0 + 2 * tq;
                wst[nxt][2 * ln]     = *(const float2*)wr;
                wst[nxt][2 * ln + 1] = *(const float2*)(wr + 8);
            }
        }

        unsigned ab[4], as[4];
        split_bf16(ast[cur][0].x, ast[cur][0].y, ab[0], as[0]);
        split_bf16(ast[cur][1].x, ast[cur][1].y, ab[1], as[1]);
        split_bf16(ast[cur][2].x, ast[cur][2].y, ab[2], as[2]);
        split_bf16(ast[cur][3].x, ast[cur][3].y, ab[3], as[3]);

#pragma unroll
        for (int nt = 0; nt < 16; nt++) {
            float4 wf = *(const float4*)&WP[((nt * 32) + lane) * 4];
            unsigned wb0 = __float_as_uint(wf.x), wb1 = __float_as_uint(wf.y);
            unsigned ws0 = __float_as_uint(wf.z), ws1 = __float_as_uint(wf.w);
            mma_bf16(acc[nt], ab, wb0, wb1);
            mma_bf16(acc[nt], as, wb0, wb1);
            mma_bf16(acc[nt], ab, ws0, ws1);
        }
    }

    const size_t cls_off = (size_t)BATCH * NPIX * CDIM;
#pragma unroll
    for (int half = 0; half < 2; half++) {
        int r = half ? r1 : r0;
        if (r >= MTOT) continue;
        int b = r / SEQ, s = r % SEQ;
#pragma unroll
        for (int nt = 0; nt < 16; nt++) {
            int col = colBase + nt * 8 + 2 * tq;
            float v0 = acc[nt][half * 2 + 0] + bias[col];
            float v1 = acc[nt][half * 2 + 1] + bias[col + 1];
            size_t dst = (s == 0)
                       ? cls_off + (size_t)b * CDIM + col
                       : ((size_t)b * NPIX + (s - 1)) * CDIM + col;
            *(float2*)&out[dst] = make_float2(v0, v1);
        }
    }
}

// ---------------------------------------------------------------------------
extern "C" void kernel_launch(void* const* d_in, const int* in_sizes, int n_in,
                              void* d_out, int out_size)
{
    const float* x      = (const float*)d_in[0];
    const float* cls    = (const float*)d_in[1];
    const float* qkv_w  = (const float*)d_in[2];
    const float* proj_w = (const float*)d_in[3];
    const float* proj_b = (const float*)d_in[4];
    const float* lepe_w = (const float*)d_in[5];
    const float* lepe_b = (const float*)d_in[6];
    float* out = (float*)d_out;

    dim3 g1((MTOT + 63) / 64, QKV_N / 128);       // 197 x 6
    qkv_gemm_tc_kernel<<<g1, 128>>>(x, cls, qkv_w);

    dim3 g2((SEQ + 127) / 128, HEADS, BATCH);     // 25 x 8 x 4
    flash_attn_tc_kernel<<<g2, 128>>>();

    lepe_kernel<<<BATCH * HW * 7, 256>>>(x, lepe_w, lepe_b);

    dim3 g4((MTOT + 63) / 64, CDIM / 128);        // 197 x 2
    proj_gemm_tc_kernel<<<g4, 128>>>(proj_w, proj_b, out);
}

// round 16
// speedup vs baseline: 4.6354x; 1.1164x over previous
#include <cuda_runtime.h>
#include <cuda_fp16.h>
#include <cstdint>

#define BATCH 4
#define HEADS 8
#define SEQ   3137          // 1 cls + 56*56
#define HD    32
#define CDIM  256
#define HW    56
#define NPIX  (HW*HW)       // 3136
#define MTOT  (BATCH*SEQ)   // 12548
#define QKV_N 768

// ---------------- bf16 / fp16 mma helpers ----------------------------------
__device__ __forceinline__ void split_bf16(float f0, float f1,
                                           unsigned &big, unsigned &sml) {
    asm("cvt.rn.bf16x2.f32 %0, %1, %2;" : "=r"(big) : "f"(f1), "f"(f0));
    float r0 = f0 - __uint_as_float(big << 16);
    float r1 = f1 - __uint_as_float(big & 0xffff0000u);
    asm("cvt.rn.bf16x2.f32 %0, %1, %2;" : "=r"(sml) : "f"(r1), "f"(r0));
}
__device__ __forceinline__ unsigned pack_f16(float f0, float f1) {
    unsigned r; asm("cvt.rn.f16x2.f32 %0, %1, %2;" : "=r"(r) : "f"(f1), "f"(f0));
    return r;
}
__device__ __forceinline__ void split_f16(float f0, float f1,
                                          unsigned &big, unsigned &sml) {
    big = pack_f16(f0, f1);
    __half2 h = *reinterpret_cast<__half2*>(&big);
    float2 bf = __half22float2(h);
    sml = pack_f16(f0 - bf.x, f1 - bf.y);
}
__device__ __forceinline__ void mma_bf16(float c[4], const unsigned a[4],
                                         unsigned b0, unsigned b1) {
    asm volatile(
        "mma.sync.aligned.m16n8k16.row.col.f32.bf16.bf16.f32 "
        "{%0,%1,%2,%3}, {%4,%5,%6,%7}, {%8,%9}, {%0,%1,%2,%3};"
        : "+f"(c[0]), "+f"(c[1]), "+f"(c[2]), "+f"(c[3])
        : "r"(a[0]), "r"(a[1]), "r"(a[2]), "r"(a[3]), "r"(b0), "r"(b1));
}
__device__ __forceinline__ void mma_f16(float c[4], const unsigned a[4],
                                        unsigned b0, unsigned b1) {
    asm volatile(
        "mma.sync.aligned.m16n8k16.row.col.f32.f16.f16.f32 "
        "{%0,%1,%2,%3}, {%4,%5,%6,%7}, {%8,%9}, {%0,%1,%2,%3};"
        : "+f"(c[0]), "+f"(c[1]), "+f"(c[2]), "+f"(c[3])
        : "r"(a[0]), "r"(a[1]), "r"(a[2]), "r"(a[3]), "r"(b0), "r"(b1));
}
__device__ __forceinline__ float ex2(float x) {
    float r; asm("ex2.approx.f32 %0, %1;" : "=f"(r) : "f"(x)); return r;
}

// ---------------- scratch (device globals; no allocation allowed) ----------
__device__ float g_Q[(size_t)BATCH*HEADS*SEQ*HD];
__device__ float g_K[(size_t)BATCH*HEADS*SEQ*HD];
__device__ float g_V[(size_t)BATCH*HEADS*SEQ*HD];
__device__ float g_O[(size_t)BATCH*SEQ*CDIM];

// ---------------------------------------------------------------------------
// Kernel 1: QKV GEMM on tensor cores (bf16 3-pass), single-barrier
// double-buffered W staging. M=12548, N=768, K=256. Block 128 thr.
// Q pre-scaled by 32^-0.5 * log2(e) (log2-domain softmax downstream).
// ---------------------------------------------------------------------------
__global__ __launch_bounds__(128) void qkv_gemm_tc_kernel(
    const float* __restrict__ x, const float* __restrict__ cls,
    const float* __restrict__ w)
{
    __shared__ float WP[2][16 * 32 * 4];   // 16 KB

    const int t    = threadIdx.x;
    const int warp = t >> 5;
    const int lane = t & 31;
    const int g    = lane >> 2;
    const int tq   = lane & 3;

    const int rowBase = blockIdx.x * 64;
    const int colBase = blockIdx.y * 128;

    const int r0 = rowBase + warp * 16 + g;
    const int r1 = r0 + 8;
    int r0c = r0 < MTOT ? r0 : MTOT - 1;
    int r1c = r1 < MTOT ? r1 : MTOT - 1;

    const float* arow0;
    const float* arow1;
    {
        int b0 = r0c / SEQ, s0 = r0c % SEQ;
        arow0 = (s0 == 0) ? (cls + (size_t)b0 * CDIM)
                          : (x + ((size_t)b0 * NPIX + (s0 - 1)) * CDIM);
        int b1 = r1c / SEQ, s1 = r1c % SEQ;
        arow1 = (s1 == 0) ? (cls + (size_t)b1 * CDIM)
                          : (x + ((size_t)b1 * NPIX + (s1 - 1)) * CDIM);
    }

    float acc[16][4];
#pragma unroll
    for (int nt = 0; nt < 16; nt++) {
        acc[nt][0] = 0.f; acc[nt][1] = 0.f; acc[nt][2] = 0.f; acc[nt][3] = 0.f;
    }

    float2 ast[2][4];
    float2 wst[8];

    // W iter0 -> regs -> WP[0]
#pragma unroll
    for (int ln = 0; ln < 4; ln++) {
        const float* wr = w + (size_t)(colBase + (warp * 4 + ln) * 8 + g) * CDIM + 2 * tq;
        wst[2 * ln]     = *(const float2*)wr;
        wst[2 * ln + 1] = *(const float2*)(wr + 8);
    }
#pragma unroll
    for (int ln = 0; ln < 4; ln++) {
        unsigned b01, s01, b89, s89;
        split_bf16(wst[2 * ln].x,     wst[2 * ln].y,     b01, s01);
        split_bf16(wst[2 * ln + 1].x, wst[2 * ln + 1].y, b89, s89);
        *(float4*)&WP[0][(((warp * 4 + ln) * 32) + lane) * 4] =
            make_float4(__uint_as_float(b01), __uint_as_float(b89),
                        __uint_as_float(s01), __uint_as_float(s89));
    }
    // A iter0, iter1; W iter1 -> regs
    ast[0][0] = *(const float2*)(arow0 + 2 * tq);
    ast[0][1] = *(const float2*)(arow1 + 2 * tq);
    ast[0][2] = *(const float2*)(arow0 + 2 * tq + 8);
    ast[0][3] = *(const float2*)(arow1 + 2 * tq + 8);
    ast[1][0] = *(const float2*)(arow0 + 16 + 2 * tq);
    ast[1][1] = *(const float2*)(arow1 + 16 + 2 * tq);
    ast[1][2] = *(const float2*)(arow0 + 16 + 2 * tq + 8);
    ast[1][3] = *(const float2*)(arow1 + 16 + 2 * tq + 8);
#pragma unroll
    for (int ln = 0; ln < 4; ln++) {
        const float* wr = w + (size_t)(colBase + (warp * 4 + ln) * 8 + g) * CDIM + 16 + 2 * tq;
        wst[2 * ln]     = *(const float2*)wr;
        wst[2 * ln + 1] = *(const float2*)(wr + 8);
    }
    __syncthreads();

#pragma unroll
    for (int iter = 0; iter < 16; iter++) {
        const int cur = iter & 1, nxt = cur ^ 1;

        unsigned ab[4], as[4];
        split_bf16(ast[cur][0].x, ast[cur][0].y, ab[0], as[0]);
        split_bf16(ast[cur][1].x, ast[cur][1].y, ab[1], as[1]);
        split_bf16(ast[cur][2].x, ast[cur][2].y, ab[2], as[2]);
        split_bf16(ast[cur][3].x, ast[cur][3].y, ab[3], as[3]);

        if (iter < 15) {   // store W(iter+1) fragments into the idle buffer
#pragma unroll
            for (int ln = 0; ln < 4; ln++) {
                unsigned b01, s01, b89, s89;
                split_bf16(wst[2 * ln].x,     wst[2 * ln].y,     b01, s01);
                split_bf16(wst[2 * ln + 1].x, wst[2 * ln + 1].y, b89, s89);
                *(float4*)&WP[nxt][(((warp * 4 + ln) * 32) + lane) * 4] =
                    make_float4(__uint_as_float(b01), __uint_as_float(b89),
                                __uint_as_float(s01), __uint_as_float(s89));
            }
        }
        if (iter < 14) {   // raw-load iter+2
            int k0 = 16 * (iter + 2);
            ast[cur][0] = *(const float2*)(arow0 + k0 + 2 * tq);
            ast[cur][1] = *(const float2*)(arow1 + k0 + 2 * tq);
            ast[cur][2] = *(const float2*)(arow0 + k0 + 2 * tq + 8);
            ast[cur][3] = *(const float2*)(arow1 + k0 + 2 * tq + 8);
#pragma unroll
            for (int ln = 0; ln < 4; ln++) {
                const float* wr = w + (size_t)(colBase + (warp * 4 + ln) * 8 + g) * CDIM + k0 + 2 * tq;
                wst[2 * ln]     = *(const float2*)wr;
                wst[2 * ln + 1] = *(const float2*)(wr + 8);
            }
        }

#pragma unroll
        for (int nt = 0; nt < 16; nt++) {
            float4 wf = *(const float4*)&WP[cur][((nt * 32) + lane) * 4];
            unsigned wb0 = __float_as_uint(wf.x), wb1 = __float_as_uint(wf.y);
            unsigned ws0 = __float_as_uint(wf.z), ws1 = __float_as_uint(wf.w);
            mma_bf16(acc[nt], ab, wb0, wb1);
            mma_bf16(acc[nt], as, wb0, wb1);
            mma_bf16(acc[nt], ab, ws0, ws1);
        }
        __syncthreads();
    }

    // epilogue: scatter into g_Q (scaled, log2 domain) / g_K / g_V
    const float scale = 0.2550348293228297f;   // 32^-0.5 * log2(e)
#pragma unroll
    for (int half = 0; half < 2; half++) {
        int r = half ? r1 : r0;
        if (r >= MTOT) continue;
        int b = r / SEQ, s = r % SEQ;
#pragma unroll
        for (int nt = 0; nt < 16; nt++) {
            int col   = colBase + nt * 8 + 2 * tq;
            int which = col >> 8;
            int f     = col & 255;
            int head  = f >> 5;
            int d     = f & 31;
            size_t dst = (((size_t)(b * HEADS + head)) * SEQ + s) * HD + d;
            float v0 = acc[nt][half * 2 + 0];
            float v1 = acc[nt][half * 2 + 1];
            if (which == 0) {
                *(float2*)&g_Q[dst] = make_float2(v0 * scale, v1 * scale);
            } else if (which == 1) {
                *(float2*)&g_K[dst] = make_float2(v0, v1);
            } else {
                *(float2*)&g_V[dst] = make_float2(v0, v1);
            }
        }
    }
}

// ---------------------------------------------------------------------------
// Flash attention staging helpers
// ---------------------------------------------------------------------------
__device__ __forceinline__ void load_k_raw(const float* __restrict__ Kg,
                                           int kbase, int warp, int g, int tq,
                                           float2 kst2[2][4]) {
#pragma unroll
    for (int ln = 0; ln < 2; ln++) {
        int key = kbase + warp * 16 + ln * 8 + g;
        if (key > SEQ - 1) key = SEQ - 1;
        const float* kr = Kg + (size_t)key * HD + 2 * tq;
        kst2[ln][0] = *(const float2*)(kr);
        kst2[ln][1] = *(const float2*)(kr + 8);
        kst2[ln][2] = *(const float2*)(kr + 16);
        kst2[ln][3] = *(const float2*)(kr + 24);
    }
}
__device__ __forceinline__ void load_v_raw(const float* __restrict__ Vg,
                                           int kbase, int warp, int g, int tq,
                                           float vst[4][4]) {
    int k0 = kbase + 16 * warp + 2 * tq;
    int ka = k0, kb2 = k0 + 1, kc2 = k0 + 8, kd = k0 + 9;
    if (ka  > SEQ - 1) ka  = SEQ - 1;
    if (kb2 > SEQ - 1) kb2 = SEQ - 1;
    if (kc2 > SEQ - 1) kc2 = SEQ - 1;
    if (kd  > SEQ - 1) kd  = SEQ - 1;
#pragma unroll
    for (int ln = 0; ln < 4; ln++) {
        int d = ln * 8 + g;
        vst[ln][0] = Vg[(size_t)ka  * HD + d];
        vst[ln][1] = Vg[(size_t)kb2 * HD + d];
        vst[ln][2] = Vg[(size_t)kc2 * HD + d];
        vst[ln][3] = Vg[(size_t)kd  * HD + d];
    }
}
__device__ __forceinline__ void store_tiles(uint4* __restrict__ KPb,
                                            uint4* __restrict__ VPb,
                                            int warp, int lane,
                                            const float2 kst2[2][4],
                                            const float vst[4][4]) {
#pragma unroll
    for (int ln = 0; ln < 2; ln++) {
#pragma unroll
        for (int kc = 0; kc < 2; kc++) {
            unsigned b01, s01, b89, s89;
            split_bf16(kst2[ln][2 * kc].x,     kst2[ln][2 * kc].y,     b01, s01);
            split_bf16(kst2[ln][2 * kc + 1].x, kst2[ln][2 * kc + 1].y, b89, s89);
            KPb[(((warp * 2 + ln) * 2 + kc) * 32) + lane] =
                make_uint4(b01, b89, s01, s89);
        }
    }
#pragma unroll
    for (int ln = 0; ln < 4; ln++) {
        unsigned vb0, vs0, vb1, vs1;
        split_f16(vst[ln][0], vst[ln][1], vb0, vs0);
        split_f16(vst[ln][2], vst[ln][3], vb1, vs1);
        VPb[((warp * 4 + ln) * 32) + lane] = make_uint4(vb0, vb1, vs0, vs1);
    }
}

// ---------------------------------------------------------------------------
// Kernel 2: flash attention. QK bf16 3-pass; PV fp16 (P single, V 2-split);
// log2-domain softmax (Q pre-scaled by log2e); double-buffered smem tiles
// with ONE barrier per chunk; pipelined gmem staging. Block 128 thr, 2/SM.
// ---------------------------------------------------------------------------
__global__ __launch_bounds__(128, 2) void flash_attn_tc_kernel()
{
    const int b  = blockIdx.z;
    const int h  = blockIdx.y;
    const int qt = blockIdx.x;

    const float* Qg = g_Q + ((size_t)(b * HEADS + h)) * SEQ * HD;
    const float* Kg = g_K + ((size_t)(b * HEADS + h)) * SEQ * HD;
    const float* Vg = g_V + ((size_t)(b * HEADS + h)) * SEQ * HD;

    __shared__ uint4 KP[2][16 * 32];   // 8 KB per buffer
    __shared__ uint4 VP[2][16 * 32];

    const int t    = threadIdx.x;
    const int warp = t >> 5;
    const int lane = t & 31;
    const int g    = lane >> 2;
    const int tq   = lane & 3;

    const int qbase = qt * 128 + warp * 32;

    // ---- resident Q fragments (bf16 big/small), 2 row-halves, 2 k16-chunks -
    unsigned qb[2][2][4], qs[2][2][4];
#pragma unroll
    for (int hb = 0; hb < 2; hb++) {
        int r0 = qbase + hb * 16 + g;     if (r0 > SEQ - 1) r0 = SEQ - 1;
        int r1 = qbase + hb * 16 + g + 8; if (r1 > SEQ - 1) r1 = SEQ - 1;
#pragma unroll
        for (int kc = 0; kc < 2; kc++) {
            const float* p0 = Qg + (size_t)r0 * HD + 16 * kc + 2 * tq;
            const float* p1 = Qg + (size_t)r1 * HD + 16 * kc + 2 * tq;
            float2 a = *(const float2*)p0;
            float2 c = *(const float2*)(p0 + 8);
            float2 d = *(const float2*)(p1 + 8);
            float2 e = *(const float2*)p1;
            split_bf16(a.x, a.y, qb[hb][kc][0], qs[hb][kc][0]);
            split_bf16(e.x, e.y, qb[hb][kc][1], qs[hb][kc][1]);
            split_bf16(c.x, c.y, qb[hb][kc][2], qs[hb][kc][2]);
            split_bf16(d.x, d.y, qb[hb][kc][3], qs[hb][kc][3]);
        }
    }

    float O[2][4][4] = {};
    float m_run[2][2] = {{-1e30f, -1e30f}, {-1e30f, -1e30f}};
    float l_run[2][2] = {{0.f, 0.f}, {0.f, 0.f}};

    const int NKT = (SEQ + 63) / 64;    // 50

    float2 kst2[2][4];
    float  vst[4][4];

    // ---- prologue: chunk0 -> buf0; chunk1 raw into regs ----
    load_k_raw(Kg, 0, warp, g, tq, kst2);
    load_v_raw(Vg, 0, warp, g, tq, vst);
    store_tiles(KP[0], VP[0], warp, lane, kst2, vst);
    if (NKT > 1) {
        load_k_raw(Kg, 64, warp, g, tq, kst2);
        load_v_raw(Vg, 64, warp, g, tq, vst);
    }
    __syncthreads();

    for (int kt = 0; kt < NKT; kt++) {
        const int kbase = kt * 64;
        const int cur = kt & 1, nxt = cur ^ 1;

        // ---- S = Q K^T from KP[cur] : 8 n-tiles, 2 k16-chunks, 3-pass bf16 -
        float s[2][8][4];
#pragma unroll
        for (int nt = 0; nt < 8; nt++) {
#pragma unroll
            for (int hb = 0; hb < 2; hb++) {
                s[hb][nt][0] = 0.f; s[hb][nt][1] = 0.f;
                s[hb][nt][2] = 0.f; s[hb][nt][3] = 0.f;
            }
#pragma unroll
            for (int kc = 0; kc < 2; kc++) {
                uint4 kf = KP[cur][((nt * 2 + kc) * 32) + lane];
#pragma unroll
                for (int hb = 0; hb < 2; hb++) {
                    mma_bf16(s[hb][nt], qb[hb][kc], kf.x, kf.y);
                    mma_bf16(s[hb][nt], qs[hb][kc], kf.x, kf.y);
                    mma_bf16(s[hb][nt], qb[hb][kc], kf.z, kf.w);
                }
            }
        }

        // ---- stage chunk kt+1 into idle buffer; prefetch chunk kt+2 ----
        if (kt + 1 < NKT) {
            store_tiles(KP[nxt], VP[nxt], warp, lane, kst2, vst);
            if (kt + 2 < NKT) {
                load_k_raw(Kg, (kt + 2) * 64, warp, g, tq, kst2);
                load_v_raw(Vg, (kt + 2) * 64, warp, g, tq, vst);
            }
        }

        // ---- mask invalid keys (only last chunk) ----
        if (kbase + 64 > SEQ) {
#pragma unroll
            for (int nt = 0; nt < 8; nt++) {
                int c = kbase + nt * 8 + 2 * tq;
#pragma unroll
                for (int hb = 0; hb < 2; hb++) {
                    if (c     >= SEQ) { s[hb][nt][0] = -1e30f; s[hb][nt][2] = -1e30f; }
                    if (c + 1 >= SEQ) { s[hb][nt][1] = -1e30f; s[hb][nt][3] = -1e30f; }
                }
            }
        }

        // ---- online softmax per half (log2 domain, raw ex2) ----
#pragma unroll
        for (int hb = 0; hb < 2; hb++) {
            float mx0 = -1e30f, mx1 = -1e30f;
#pragma unroll
            for (int nt = 0; nt < 8; nt++) {
                mx0 = fmaxf(mx0, fmaxf(s[hb][nt][0], s[hb][nt][1]));
                mx1 = fmaxf(mx1, fmaxf(s[hb][nt][2], s[hb][nt][3]));
            }
            mx0 = fmaxf(mx0, __shfl_xor_sync(0xffffffffu, mx0, 1));
            mx0 = fmaxf(mx0, __shfl_xor_sync(0xffffffffu, mx0, 2));
            mx1 = fmaxf(mx1, __shfl_xor_sync(0xffffffffu, mx1, 1));
            mx1 = fmaxf(mx1, __shfl_xor_sync(0xffffffffu, mx1, 2));
            float mn0 = fmaxf(m_run[hb][0], mx0);
            float mn1 = fmaxf(m_run[hb][1], mx1);
            float corr0 = ex2(m_run[hb][0] - mn0);
            float corr1 = ex2(m_run[hb][1] - mn1);

            float ls0 = 0.f, ls1 = 0.f;
#pragma unroll
            for (int nt = 0; nt < 8; nt++) {
                s[hb][nt][0] = ex2(s[hb][nt][0] - mn0);
                s[hb][nt][1] = ex2(s[hb][nt][1] - mn0);
                s[hb][nt][2] = ex2(s[hb][nt][2] - mn1);
                s[hb][nt][3] = ex2(s[hb][nt][3] - mn1);
                ls0 += s[hb][nt][0] + s[hb][nt][1];
                ls1 += s[hb][nt][2] + s[hb][nt][3];
            }
            ls0 += __shfl_xor_sync(0xffffffffu, ls0, 1);
            ls0 += __shfl_xor_sync(0xffffffffu, ls0, 2);
            ls1 += __shfl_xor_sync(0xffffffffu, ls1, 1);
            ls1 += __shfl_xor_sync(0xffffffffu, ls1, 2);
            l_run[hb][0] = l_run[hb][0] * corr0 + ls0;  m_run[hb][0] = mn0;
            l_run[hb][1] = l_run[hb][1] * corr1 + ls1;  m_run[hb][1] = mn1;

#pragma unroll
            for (int nt = 0; nt < 4; nt++) {
                O[hb][nt][0] *= corr0; O[hb][nt][1] *= corr0;
                O[hb][nt][2] *= corr1; O[hb][nt][3] *= corr1;
            }
        }

        // ---- O += P V : P single fp16 (own C-frag), V 2-split fp16 ----
#pragma unroll
        for (int kc = 0; kc < 4; kc++) {
            unsigned pp[2][4];
#pragma unroll
            for (int hb = 0; hb < 2; hb++) {
                pp[hb][0] = pack_f16(s[hb][2*kc][0],   s[hb][2*kc][1]);
                pp[hb][1] = pack_f16(s[hb][2*kc][2],   s[hb][2*kc][3]);
                pp[hb][2] = pack_f16(s[hb][2*kc+1][0], s[hb][2*kc+1][1]);
                pp[hb][3] = pack_f16(s[hb][2*kc+1][2], s[hb][2*kc+1][3]);
            }
#pragma unroll
            for (int nt = 0; nt < 4; nt++) {
                uint4 vf = VP[cur][((kc * 4 + nt) * 32) + lane];
#pragma unroll
                for (int hb = 0; hb < 2; hb++) {
                    mma_f16(O[hb][nt], pp[hb], vf.x, vf.y);   // P * V_big
                    mma_f16(O[hb][nt], pp[hb], vf.z, vf.w);   // P * V_small
                }
            }
        }
        __syncthreads();
    }

    // ---- epilogue ----
#pragma unroll
    for (int hb = 0; hb < 2; hb++) {
        float inv0 = 1.f / l_run[hb][0], inv1 = 1.f / l_run[hb][1];
        int r0 = qbase + hb * 16 + g;
        int r1 = qbase + hb * 16 + g + 8;
#pragma unroll
        for (int nt = 0; nt < 4; nt++) {
            int col = h * HD + nt * 8 + 2 * tq;
            if (r0 < SEQ) {
                float2 v = make_float2(O[hb][nt][0] * inv0, O[hb][nt][1] * inv0);
                *(float2*)&g_O[((size_t)b * SEQ + r0) * CDIM + col] = v;
            }
            if (r1 < SEQ) {
                float2 v = make_float2(O[hb][nt][2] * inv1, O[hb][nt][3] * inv1);
                *(float2*)&g_O[((size_t)b * SEQ + r1) * CDIM + col] = v;
            }
        }
    }
}

// ---------------------------------------------------------------------------
// Kernel 3: depthwise 5x5 LePE (NHWC, SAME), adds into g_O rows 1..3136.
// ---------------------------------------------------------------------------
__global__ __launch_bounds__(256) void lepe_kernel(
    const float* __restrict__ x, const float* __restrict__ w,
    const float* __restrict__ bias)
{
    __shared__ float ws[CDIM * 25];
    const int c = threadIdx.x;
    for (int idx = c; idx < CDIM * 25; idx += 256) ws[idx] = w[idx];
    __syncthreads();

    const int blk  = blockIdx.x;         // 0 .. 4*56*7-1
    const int b    = blk / (HW * 7);
    const int rem  = blk % (HW * 7);
    const int hh   = rem / 7;
    const int ww0  = (rem % 7) * 8;
    const float bc = bias[c];

#pragma unroll
    for (int p = 0; p < 8; p++) {
        int ww = ww0 + p;
        float sum = bc;
#pragma unroll
        for (int dy = 0; dy < 5; dy++) {
            int y = hh + dy - 2;
            if (y < 0 || y >= HW) continue;
#pragma unroll
            for (int dx = 0; dx < 5; dx++) {
                int xx = ww + dx - 2;
                if (xx < 0 || xx >= HW) continue;
                sum = fmaf(x[(((size_t)b * HW + y) * HW + xx) * CDIM + c],
                           ws[c * 25 + dy * 5 + dx], sum);
            }
        }
        int hw = hh * HW + ww;
        g_O[((size_t)b * SEQ + 1 + hw) * CDIM + c] += sum;
    }
}

// ---------------------------------------------------------------------------
// Kernel 4: proj GEMM on tensor cores (bf16 3-pass), single-barrier
// double-buffered W staging. M=12548, N=256, K=256.
// ---------------------------------------------------------------------------
__global__ __launch_bounds__(128) void proj_gemm_tc_kernel(
    const float* __restrict__ w, const float* __restrict__ bias,
    float* __restrict__ out)
{
    __shared__ float WP[2][16 * 32 * 4];   // 16 KB

    const int t    = threadIdx.x;
    const int warp = t >> 5;
    const int lane = t & 31;
    const int g    = lane >> 2;
    const int tq   = lane & 3;

    const int rowBase = blockIdx.x * 64;
    const int colBase = blockIdx.y * 128;

    const int r0 = rowBase + warp * 16 + g;
    const int r1 = r0 + 8;
    int r0c = r0 < MTOT ? r0 : MTOT - 1;
    int r1c = r1 < MTOT ? r1 : MTOT - 1;
    const float* arow0 = g_O + (size_t)r0c * CDIM;
    const float* arow1 = g_O + (size_t)r1c * CDIM;

    float acc[16][4];
#pragma unroll
    for (int nt = 0; nt < 16; nt++) {
        acc[nt][0] = 0.f; acc[nt][1] = 0.f; acc[nt][2] = 0.f; acc[nt][3] = 0.f;
    }

    float2 ast[2][4];
    float2 wst[8];

#pragma unroll
    for (int ln = 0; ln < 4; ln++) {
        const float* wr = w + (size_t)(colBase + (warp * 4 + ln) * 8 + g) * CDIM + 2 * tq;
        wst[2 * ln]     = *(const float2*)wr;
        wst[2 * ln + 1] = *(const float2*)(wr + 8);
    }
#pragma unroll
    for (int ln = 0; ln < 4; ln++) {
        unsigned b01, s01, b89, s89;
        split_bf16(wst[2 * ln].x,     wst[2 * ln].y,     b01, s01);
        split_bf16(wst[2 * ln + 1].x, wst[2 * ln + 1].y, b89, s89);
        *(float4*)&WP[0][(((warp * 4 + ln) * 32) + lane) * 4] =
            make_float4(__uint_as_float(b01), __uint_as_float(b89),
                        __uint_as_float(s01), __uint_as_float(s89));
    }
    ast[0][0] = *(const float2*)(arow0 + 2 * tq);
    ast[0][1] = *(const float2*)(arow1 + 2 * tq);
    ast[0][2] = *(const float2*)(arow0 + 2 * tq + 8);
    ast[0][3] = *(const float2*)(arow1 + 2 * tq + 8);
    ast[1][0] = *(const float2*)(arow0 + 16 + 2 * tq);
    ast[1][1] = *(const float2*)(arow1 + 16 + 2 * tq);
    ast[1][2] = *(const float2*)(arow0 + 16 + 2 * tq + 8);
    ast[1][3] = *(const float2*)(arow1 + 16 + 2 * tq + 8);
#pragma unroll
    for (int ln = 0; ln < 4; ln++) {
        const float* wr = w + (size_t)(colBase + (warp * 4 + ln) * 8 + g) * CDIM + 16 + 2 * tq;
        wst[2 * ln]     = *(const float2*)wr;
        wst[2 * ln + 1] = *(const float2*)(wr + 8);
    }
    __syncthreads();

#pragma unroll
    for (int iter = 0; iter < 16; iter++) {
        const int cur = iter & 1, nxt = cur ^ 1;

        unsigned ab[4], as[4];
        split_bf16(ast[cur][0].x, ast[cur][0].y, ab[0], as[0]);
        split_bf16(ast[cur][1].x, ast[cur][1].y, ab[1], as[1]);
        split_bf16(ast[cur][2].x, ast[cur][2].y, ab[2], as[2]);
        split_bf16(ast[cur][3].x, ast[cur][3].y, ab[3], as[3]);

        if (iter < 15) {
#pragma unroll
            for (int ln = 0; ln < 4; ln++) {
                unsigned b01, s01, b89, s89;
                split_bf16(wst[2 * ln].x,     wst[2 * ln].y,     b01, s01);
                split_bf16(wst[2 * ln + 1].x, wst[2 * ln + 1].y, b89, s89);
                *(float4*)&WP[nxt][(((warp * 4 + ln) * 32) + lane) * 4] =
                    make_float4(__uint_as_float(b01), __uint_as_float(b89),
                                __uint_as_float(s01), __uint_as_float(s89));
            }
        }
        if (iter < 14) {
            int k0 = 16 * (iter + 2);
            ast[cur][0] = *(const float2*)(arow0 + k0 + 2 * tq);
            ast[cur][1] = *(const float2*)(arow1 + k0 + 2 * tq);
            ast[cur][2] = *(const float2*)(arow0 + k0 + 2 * tq + 8);
            ast[cur][3] = *(const float2*)(arow1 + k0 + 2 * tq + 8);
#pragma unroll
            for (int ln = 0; ln < 4; ln++) {
                const float* wr = w + (size_t)(colBase + (warp * 4 + ln) * 8 + g) * CDIM + k0 + 2 * tq;
                wst[2 * ln]     = *(const float2*)wr;
                wst[2 * ln + 1] = *(const float2*)(wr + 8);
            }
        }

#pragma unroll
        for (int nt = 0; nt < 16; nt++) {
            float4 wf = *(const float4*)&WP[cur][((nt * 32) + lane) * 4];
            unsigned wb0 = __float_as_uint(wf.x), wb1 = __float_as_uint(wf.y);
            unsigned ws0 = __float_as_uint(wf.z), ws1 = __float_as_uint(wf.w);
            mma_bf16(acc[nt], ab, wb0, wb1);
            mma_bf16(acc[nt], as, wb0, wb1);
            mma_bf16(acc[nt], ab, ws0, ws1);
        }
        __syncthreads();
    }

    const size_t cls_off = (size_t)BATCH * NPIX * CDIM;
#pragma unroll
    for (int half = 0; half < 2; half++) {
        int r = half ? r1 : r0;
        if (r >= MTOT) continue;
        int b = r / SEQ, s = r % SEQ;
#pragma unroll
        for (int nt = 0; nt < 16; nt++) {
            int col = colBase + nt * 8 + 2 * tq;
            float v0 = acc[nt][half * 2 + 0] + bias[col];
            float v1 = acc[nt][half * 2 + 1] + bias[col + 1];
            size_t dst = (s == 0)
                       ? cls_off + (size_t)b * CDIM + col
                       : ((size_t)b * NPIX + (s - 1)) * CDIM + col;
            *(float2*)&out[dst] = make_float2(v0, v1);
        }
    }
}

// ---------------------------------------------------------------------------
extern "C" void kernel_launch(void* const* d_in, const int* in_sizes, int n_in,
                              void* d_out, int out_size)
{
    const float* x      = (const float*)d_in[0];
    const float* cls    = (const float*)d_in[1];
    const float* qkv_w  = (const float*)d_in[2];
    const float* proj_w = (const float*)d_in[3];
    const float* proj_b = (const float*)d_in[4];
    const float* lepe_w = (const float*)d_in[5];
    const float* lepe_b = (const float*)d_in[6];
    float* out = (float*)d_out;

    dim3 g1((MTOT + 63) / 64, QKV_N / 128);       // 197 x 6
    qkv_gemm_tc_kernel<<<g1, 128>>>(x, cls, qkv_w);

    dim3 g2((SEQ + 127) / 128, HEADS, BATCH);     // 25 x 8 x 4
    flash_attn_tc_kernel<<<g2, 128>>>();

    lepe_kernel<<<BATCH * HW * 7, 256>>>(x, lepe_w, lepe_b);

    dim3 g4((MTOT + 63) / 64, CDIM / 128);        // 197 x 2
    proj_gemm_tc_kernel<<<g4, 128>>>(proj_w, proj_b, out);
}